// round 11
// baseline (speedup 1.0000x reference)
#include <cuda_runtime.h>
#include <cuda_bf16.h>
#include <cuda_fp16.h>
#include <cstdint>

#define BB 4
#define NN 1024
#define DD 512
#define HH 8
#define EE 5
#define HDIM 64
#define QT 128
#define KT 64
#define NTILES (NN / KT)
#define L2E 1.4426950408889634f

// ---------------- scratch (device globals; no allocation allowed) ----------------
__device__ float g_v[BB * HH * NN * HDIM];
__device__ int   g_mask[BB * NN];
__device__ int   g_any[BB];
__device__ __half g_G16[(size_t)BB * HH * NN * NN];   // gate*bias*log2e, fp16
__device__ __nv_bfloat16 g_qhi[BB * HH * NN * HDIM], g_qlo[BB * HH * NN * HDIM];
__device__ __nv_bfloat16 g_khi[BB * HH * NN * HDIM], g_klo[BB * HH * NN * HDIM];
__device__ __nv_bfloat16 g_vthi[BB * HH * NN * HDIM], g_vtlo[BB * HH * NN * HDIM];
__device__ __nv_bfloat16 g_xhi[BB * NN * DD],   g_xlo[BB * NN * DD];
__device__ __nv_bfloat16 g_wqkvhi[3 * DD * DD], g_wqkvlo[3 * DD * DD];
__device__ __nv_bfloat16 g_atthi[BB * NN * DD], g_attlo[BB * NN * DD];
__device__ __nv_bfloat16 g_wprojhi[DD * DD],    g_wprojlo[DD * DD];

#define NX (BB * NN * DD)
#define NW (3 * DD * DD)
#define NP (DD * DD)

// ---------------- helpers ----------------
__device__ __forceinline__ uint32_t smem_u32(const void* p) {
    return (uint32_t)__cvta_generic_to_shared(p);
}
__device__ __forceinline__ void ldsm4(uint32_t& r0, uint32_t& r1, uint32_t& r2, uint32_t& r3,
                                      uint32_t a) {
    asm volatile("ldmatrix.sync.aligned.m8n8.x4.shared.b16 {%0,%1,%2,%3}, [%4];"
                 : "=r"(r0), "=r"(r1), "=r"(r2), "=r"(r3) : "r"(a));
}
__device__ __forceinline__ void mma16816(float* c, uint32_t a0, uint32_t a1, uint32_t a2,
                                         uint32_t a3, uint32_t b0, uint32_t b1) {
    asm volatile(
        "mma.sync.aligned.m16n8k16.row.col.f32.bf16.bf16.f32 "
        "{%0,%1,%2,%3}, {%4,%5,%6,%7}, {%8,%9}, {%0,%1,%2,%3};"
        : "+f"(c[0]), "+f"(c[1]), "+f"(c[2]), "+f"(c[3])
        : "r"(a0), "r"(a1), "r"(a2), "r"(a3), "r"(b0), "r"(b1));
}
__device__ __forceinline__ void cp_async16(uint32_t saddr, const void* gaddr) {
    asm volatile("cp.async.ca.shared.global [%0], [%1], 16;" :: "r"(saddr), "l"(gaddr));
}
__device__ __forceinline__ void cp_commit() {
    asm volatile("cp.async.commit_group;" ::: "memory");
}
template <int N>
__device__ __forceinline__ void cp_wait() {
    asm volatile("cp.async.wait_group %0;" :: "n"(N) : "memory");
}
__device__ __forceinline__ float fexp2(float x) {
    float y;
    asm("ex2.approx.ftz.f32 %0, %1;" : "=f"(y) : "f"(x));
    return y;
}
__device__ __forceinline__ void pack_hilo(float p0, float p1, uint32_t& hi, uint32_t& lo) {
    __nv_bfloat16 h0 = __float2bfloat16(p0), h1 = __float2bfloat16(p1);
    hi = ((uint32_t)__bfloat16_as_ushort(h1) << 16) | (uint32_t)__bfloat16_as_ushort(h0);
    __nv_bfloat16 g0 = __float2bfloat16(p0 - __bfloat162float(h0));
    __nv_bfloat16 g1 = __float2bfloat16(p1 - __bfloat162float(h1));
    lo = ((uint32_t)__bfloat16_as_ushort(g1) << 16) | (uint32_t)__bfloat16_as_ushort(g0);
}

// ---------------- kernel 0: mask canonicalization ----------------
__global__ void mask_prep_kernel(const unsigned* __restrict__ mraw) {
    __shared__ int s_int, s_float;
    __shared__ int s_any[BB];
    int t = threadIdx.x;
    if (t == 0) { s_int = 1; s_float = 1; }
    if (t < BB) s_any[t] = 0;
    __syncthreads();
    unsigned v = mraw[t];
    if (v > 1u) atomicAnd(&s_int, 0);
    if (!(v == 0u || v == 0x3F800000u)) atomicAnd(&s_float, 0);
    __syncthreads();
    int mode = s_int ? 0 : (s_float ? 1 : 2);
    for (int i = t; i < BB * NN; i += 1024) {
        int val;
        if (mode == 0)      val = ((const int*)mraw)[i];
        else if (mode == 1) val = (((const unsigned*)mraw)[i] != 0u);
        else                val = ((const unsigned char*)mraw)[i];
        val = val ? 1 : 0;
        g_mask[i] = val;
        if (val) atomicOr(&s_any[i >> 10], 1);
    }
    __syncthreads();
    if (t < BB) g_any[t] = s_any[t];
}

// ---------------- kernel 0b: fused fp32 -> bf16 hi/lo split ----------------
__global__ void cvt_all_kernel(const float* __restrict__ x,
                               const float* __restrict__ wqkv,
                               const float* __restrict__ wproj) {
    int i = blockIdx.x * 256 + threadIdx.x;
    const float* src;
    __nv_bfloat16 *hi, *lo;
    int idx;
    if (i < NX) { src = x; hi = g_xhi; lo = g_xlo; idx = i; }
    else if (i < NX + NW) { src = wqkv; hi = g_wqkvhi; lo = g_wqkvlo; idx = i - NX; }
    else if (i < NX + NW + NP) { src = wproj; hi = g_wprojhi; lo = g_wprojlo; idx = i - NX - NW; }
    else return;
    float v = src[idx];
    __nv_bfloat16 h = __float2bfloat16(v);
    hi[idx] = h;
    lo[idx] = __float2bfloat16(v - __bfloat162float(h));
}

// ---------------- kernel 0c: edge -> G16 = sigmoid(.)*bias*log2e (fp16) ----------------
__global__ __launch_bounds__(256) void edge_prep_kernel(const float* __restrict__ edge,
                                                        const float* __restrict__ w_ep,
                                                        const float* __restrict__ w_eg,
                                                        const float* __restrict__ b_eg) {
    const int m = blockIdx.x * 256 + threadIdx.x;
    const int n = blockIdx.y, b = blockIdx.z;
    const float* ep = edge + ((size_t)(b * NN + n) * NN + m) * EE;
    float e0 = __ldg(ep), e1 = __ldg(ep + 1), e2 = __ldg(ep + 2),
          e3 = __ldg(ep + 3), e4 = __ldg(ep + 4);
#pragma unroll
    for (int h = 0; h < HH; h++) {
        float biasv = e0 * __ldg(&w_ep[h * EE + 0]);
        biasv = fmaf(e1, __ldg(&w_ep[h * EE + 1]), biasv);
        biasv = fmaf(e2, __ldg(&w_ep[h * EE + 2]), biasv);
        biasv = fmaf(e3, __ldg(&w_ep[h * EE + 3]), biasv);
        biasv = fmaf(e4, __ldg(&w_ep[h * EE + 4]), biasv);
        float gv = fmaf(e0, __ldg(&w_eg[h * EE + 0]), __ldg(&b_eg[h]));
        gv = fmaf(e1, __ldg(&w_eg[h * EE + 1]), gv);
        gv = fmaf(e2, __ldg(&w_eg[h * EE + 2]), gv);
        gv = fmaf(e3, __ldg(&w_eg[h * EE + 3]), gv);
        gv = fmaf(e4, __ldg(&w_eg[h * EE + 4]), gv);
        float gate = __fdividef(1.f, 1.f + __expf(-gv));
        g_G16[((size_t)(b * HH + h) * NN + n) * NN + m] = __float2half(gate * biasv * L2E);
    }
}

// ---------------- mma.sync bf16x3 GEMM — fused 3-term single K-pass ----------------
// Chunk = 32 K-cols. Smem row (128B) = [hi 32 cols | lo 32 cols], 8x16B units, XOR swizzle.
// Per k16: ldsm Ahi/Alo/Bhi/Blo (12x ldsm4) -> 48 mma (hh + hl + lh). 2 stages x 32KB.
__global__ __launch_bounds__(256) void mma_gemm_kernel(const float* __restrict__ bias,
                                                       float* __restrict__ outp, int mode) {
    extern __shared__ __align__(128) char sm[];
    const int tid = threadIdx.x;
    const int wid = tid >> 5, lane = tid & 31;
    const int wm = wid >> 1, wn = wid & 1;
    const int mb = blockIdx.y, cb = blockIdx.x;

    const __nv_bfloat16* Ahi = (mode == 0) ? g_xhi : g_atthi;
    const __nv_bfloat16* Alo = (mode == 0) ? g_xlo : g_attlo;
    const __nv_bfloat16* Bhi = (mode == 0) ? g_wqkvhi : g_wprojhi;
    const __nv_bfloat16* Blo = (mode == 0) ? g_wqkvlo : g_wprojlo;

    const uint32_t sbase = smem_u32(sm);

    int arow[2], axc[2];
#pragma unroll
    for (int mt = 0; mt < 2; mt++) {
        int r = wm * 32 + mt * 16 + (lane & 15);
        arow[mt] = r * 128;
        axc[mt] = r & 7;
    }
    const int akh = lane >> 4;
    int brow[4], bxc[4];
#pragma unroll
    for (int j = 0; j < 4; j++) {
        int r = wn * 64 + j * 16 + ((lane >> 4) << 3) + (lane & 7);
        brow[j] = r * 128;
        bxc[j] = r & 7;
    }
    const int bkh = (lane >> 3) & 1;

    float acc[2][8][4];
#pragma unroll
    for (int mt = 0; mt < 2; mt++)
#pragma unroll
        for (int n8 = 0; n8 < 8; n8++)
#pragma unroll
            for (int q = 0; q < 4; q++) acc[mt][n8][q] = 0.f;

    const int NC = 16;   // 16 chunks x 32 K-cols = K 512
    auto load_chunk = [&](int c, int stage) {
        uint32_t st = sbase + stage * 32768;
#pragma unroll
        for (int u8 = 0; u8 < 8; u8++) {
            int u = tid * 8 + u8;
            int isB = u >> 10;
            int uu = u & 1023;
            int r = uu >> 3, ch = uu & 7;
            const __nv_bfloat16* base = isB ? ((ch < 4) ? Bhi : Blo)
                                            : ((ch < 4) ? Ahi : Alo);
            int cc = ch & 3;
            const __nv_bfloat16* src =
                base + (size_t)((isB ? cb : mb) * 128 + r) * DD + c * 32 + cc * 8;
            uint32_t sa = st + isB * 16384 + r * 128 + ((ch ^ (r & 7)) << 4);
            cp_async16(sa, src);
        }
        cp_commit();
    };

    load_chunk(0, 0);
    for (int c = 0; c < NC; c++) {
        if (c + 1 < NC) load_chunk(c + 1, (c + 1) & 1);
        if (c + 1 < NC) cp_wait<1>(); else cp_wait<0>();
        __syncthreads();
        uint32_t sA = sbase + (c & 1) * 32768;
        uint32_t sB = sA + 16384;
#pragma unroll
        for (int t = 0; t < 2; t++) {
            uint32_t ah[2][4], al_[2][4];
#pragma unroll
            for (int mt = 0; mt < 2; mt++) {
                uint32_t adh = sA + arow[mt] + (((t * 2 + akh) ^ axc[mt]) << 4);
                uint32_t adl = sA + arow[mt] + (((4 + t * 2 + akh) ^ axc[mt]) << 4);
                ldsm4(ah[mt][0], ah[mt][1], ah[mt][2], ah[mt][3], adh);
                ldsm4(al_[mt][0], al_[mt][1], al_[mt][2], al_[mt][3], adl);
            }
#pragma unroll
            for (int j = 0; j < 4; j++) {
                uint32_t bh0, bh1, bh2, bh3, bl0, bl1, bl2, bl3;
                ldsm4(bh0, bh1, bh2, bh3, sB + brow[j] + (((t * 2 + bkh) ^ bxc[j]) << 4));
                ldsm4(bl0, bl1, bl2, bl3, sB + brow[j] + (((4 + t * 2 + bkh) ^ bxc[j]) << 4));
                // hh
                mma16816(acc[0][2 * j],     ah[0][0], ah[0][1], ah[0][2], ah[0][3], bh0, bh1);
                mma16816(acc[0][2 * j + 1], ah[0][0], ah[0][1], ah[0][2], ah[0][3], bh2, bh3);
                mma16816(acc[1][2 * j],     ah[1][0], ah[1][1], ah[1][2], ah[1][3], bh0, bh1);
                mma16816(acc[1][2 * j + 1], ah[1][0], ah[1][1], ah[1][2], ah[1][3], bh2, bh3);
                // hl
                mma16816(acc[0][2 * j],     ah[0][0], ah[0][1], ah[0][2], ah[0][3], bl0, bl1);
                mma16816(acc[0][2 * j + 1], ah[0][0], ah[0][1], ah[0][2], ah[0][3], bl2, bl3);
                mma16816(acc[1][2 * j],     ah[1][0], ah[1][1], ah[1][2], ah[1][3], bl0, bl1);
                mma16816(acc[1][2 * j + 1], ah[1][0], ah[1][1], ah[1][2], ah[1][3], bl2, bl3);
                // lh
                mma16816(acc[0][2 * j],     al_[0][0], al_[0][1], al_[0][2], al_[0][3], bh0, bh1);
                mma16816(acc[0][2 * j + 1], al_[0][0], al_[0][1], al_[0][2], al_[0][3], bh2, bh3);
                mma16816(acc[1][2 * j],     al_[1][0], al_[1][1], al_[1][2], al_[1][3], bh0, bh1);
                mma16816(acc[1][2 * j + 1], al_[1][0], al_[1][1], al_[1][2], al_[1][3], bh2, bh3);
            }
        }
        __syncthreads();
    }

    const int colw = cb * 128 + wn * 64;
    const int roww = mb * 128 + wm * 32;
#pragma unroll
    for (int mt = 0; mt < 2; mt++) {
#pragma unroll
        for (int n8 = 0; n8 < 8; n8++) {
            int col = colw + n8 * 8 + (lane & 3) * 2;
            int row = roww + mt * 16 + (lane >> 2);
            if (mode == 0) {
                int sect = col >> 9, d = col & 511;
                int h2 = d >> 6, hd = d & 63;
                int b2 = row >> 10, n = row & 1023;
                if (sect < 2) {
                    __nv_bfloat16* dh = (sect == 0) ? g_qhi : g_khi;
                    __nv_bfloat16* dl = (sect == 0) ? g_qlo : g_klo;
                    int ch = (hd >> 3) ^ (row & 7);
                    size_t e0 = ((size_t)(b2 * HH + h2) * NN + n) * HDIM + (ch << 3) + (hd & 7);
                    uint32_t hi, lo;
                    pack_hilo(acc[mt][n8][0], acc[mt][n8][1], hi, lo);
                    *(uint32_t*)&dh[e0] = hi;
                    *(uint32_t*)&dl[e0] = lo;
                    pack_hilo(acc[mt][n8][2], acc[mt][n8][3], hi, lo);
                    *(uint32_t*)&dh[e0 + 8 * HDIM] = hi;
                    *(uint32_t*)&dl[e0 + 8 * HDIM] = lo;
                } else {
                    size_t base = ((size_t)(b2 * HH + h2) * NN + n) * HDIM + hd;
                    *(float2*)&g_v[base] = make_float2(acc[mt][n8][0], acc[mt][n8][1]);
                    *(float2*)&g_v[base + 8 * HDIM] = make_float2(acc[mt][n8][2], acc[mt][n8][3]);
                }
            } else {
                float b0 = bias[col], b1 = bias[col + 1];
                *(float2*)&outp[(size_t)row * DD + col] =
                    make_float2(acc[mt][n8][0] + b0, acc[mt][n8][1] + b1);
                *(float2*)&outp[(size_t)(row + 8) * DD + col] =
                    make_float2(acc[mt][n8][2] + b0, acc[mt][n8][3] + b1);
            }
        }
    }
}

// ---------------- kernel 1b: V transpose -> pre-swizzled bf16 hi/lo tiles ----------------
__global__ __launch_bounds__(256) void vprep_kernel() {
    __shared__ float Vf[64][68];
    const int t = blockIdx.x, bh = blockIdx.y;
    const int tid = threadIdx.x;
    const int m0 = t * KT;
    const float* src = g_v + ((size_t)bh * NN + m0) * HDIM;
    for (int u = tid; u < 1024; u += 256) {
        int key = u >> 4, c4 = (u & 15) * 4;
        *(float4*)&Vf[key][c4] = *(const float4*)(src + key * HDIM + c4);
    }
    __syncthreads();
    __nv_bfloat16* dh = g_vthi + (((size_t)bh * NTILES + t) * 64) * 64;
    __nv_bfloat16* dl = g_vtlo + (((size_t)bh * NTILES + t) * 64) * 64;
    for (int u = tid; u < 1024; u += 256) {
        int d = u >> 4, k4 = (u & 15) * 4;
        uint32_t h0, l0, h1, l1;
        pack_hilo(Vf[k4 + 0][d], Vf[k4 + 1][d], h0, l0);
        pack_hilo(Vf[k4 + 2][d], Vf[k4 + 3][d], h1, l1);
        int chp = (k4 >> 3) ^ (d & 7);
        size_t off = (size_t)d * 64 + (chp << 3) + (k4 & 7);
        *(uint2*)&dh[off] = make_uint2(h0, h1);
        *(uint2*)&dl[off] = make_uint2(l0, l1);
    }
}

// ---------------- kernel 2: tensor-core edge-aware flash attention ----------------
__global__ __launch_bounds__(256, 2) void attn_kernel() {
    extern __shared__ __align__(128) char smraw[];
    const uint32_t sb = smem_u32(smraw);
    const uint32_t uQh = sb, uQl = sb + 16384;
    int* skm = (int*)(smraw + 98304);

    const int b = blockIdx.z, h = blockIdx.y, qt = blockIdx.x;
    const int bh = b * HH + h;
    const int n0 = qt * QT;
    const int tid = threadIdx.x;
    const int lane = tid & 31;
    const int w = tid >> 5;
    const int wq0 = w * 16;
    const float SCALE = 0.125f * L2E;

    const int anyv = g_any[b];

    const __nv_bfloat16* qh = g_qhi + ((size_t)bh * NN + n0) * HDIM;
    const __nv_bfloat16* ql = g_qlo + ((size_t)bh * NN + n0) * HDIM;
    const __nv_bfloat16* kh = g_khi + (size_t)bh * NN * HDIM;
    const __nv_bfloat16* kl = g_klo + (size_t)bh * NN * HDIM;
    const __nv_bfloat16* vh = g_vthi + (size_t)bh * NN * HDIM;
    const __nv_bfloat16* vl = g_vtlo + (size_t)bh * NN * HDIM;

    auto issue_tile = [&](int t, int st) {
        uint32_t base = sb + 32768 + st * 32768;
        size_t ko = (size_t)t * KT * HDIM;
#pragma unroll
        for (int i = 0; i < 2; i++) {
            int u = tid * 2 + i;
            cp_async16(base + u * 16, kh + ko + u * 8);
            cp_async16(base + 8192 + u * 16, kl + ko + u * 8);
            cp_async16(base + 16384 + u * 16, vh + ko + u * 8);
            cp_async16(base + 24576 + u * 16, vl + ko + u * 8);
        }
        if (tid < 16) cp_async16(smem_u32(skm + st * 64) + tid * 16,
                                 g_mask + b * NN + t * KT + tid * 4);
    };

#pragma unroll
    for (int i = 0; i < 4; i++) {
        int u = tid * 4 + i;
        cp_async16(uQh + u * 16, qh + u * 8);
        cp_async16(uQl + u * 16, ql + u * 8);
    }
    issue_tile(0, 0);
    cp_commit();
    issue_tile(1, 1);
    cp_commit();

    const int r_lo = lane >> 2;
    const int nr0 = n0 + wq0 + r_lo;
    const int nr1 = nr0 + 8;
    const int qv0 = g_mask[b * NN + nr0];
    const int qv1 = g_mask[b * NN + nr1];
    const bool rowv0 = qv0 && anyv;
    const bool rowv1 = qv1 && anyv;

    float accO[8][4];
#pragma unroll
    for (int j = 0; j < 8; j++)
#pragma unroll
        for (int q = 0; q < 4; q++) accO[j][q] = 0.f;
    float mr0 = -1e30f, mr1 = -1e30f, sr0 = 0.f, sr1 = 0.f;

    const __half* Grow0 = g_G16 + ((size_t)bh * NN + nr0) * NN;
    const __half* Grow1 = g_G16 + ((size_t)bh * NN + nr1) * NN;

    for (int t = 0; t < NTILES; t++) {
        cp_wait<1>();
        __syncthreads();
        const int st = t & 1;
        const int m0 = t * KT;
        const uint32_t uKh = sb + 32768 + st * 32768;
        const uint32_t uKl = uKh + 8192;
        const uint32_t uVh = uKh + 16384;
        const uint32_t uVl = uKh + 24576;
        const int* skm_st = skm + st * 64;

        float accS[8][4];
#pragma unroll
        for (int j = 0; j < 8; j++)
#pragma unroll
            for (int q = 0; q < 4; q++) accS[j][q] = 0.f;

#pragma unroll
        for (int s = 0; s < 4; s++) {
            int ra = wq0 + (lane & 15);
            int cha = (s * 2 + (lane >> 4)) ^ (ra & 7);
            uint32_t aoff = (uint32_t)(ra * 64 + (cha << 3)) * 2;
            uint32_t ah[4], al_[4];
            ldsm4(ah[0], ah[1], ah[2], ah[3], uQh + aoff);
            ldsm4(al_[0], al_[1], al_[2], al_[3], uQl + aoff);
            int rb = ((lane >> 4) << 3) + (lane & 7);
            int khb = s * 2 + ((lane >> 3) & 1);
#pragma unroll
            for (int g = 0; g < 4; g++) {
                int rn = g * 16 + rb;
                uint32_t boff = (uint32_t)(rn * 64 + ((khb ^ (rn & 7)) << 3)) * 2;
                uint32_t bh0, bh1, bh2, bh3, bl0, bl1, bl2, bl3;
                ldsm4(bh0, bh1, bh2, bh3, uKh + boff);
                ldsm4(bl0, bl1, bl2, bl3, uKl + boff);
                mma16816(accS[2 * g],     ah[0], ah[1], ah[2], ah[3], bh0, bh1);
                mma16816(accS[2 * g + 1], ah[0], ah[1], ah[2], ah[3], bh2, bh3);
                mma16816(accS[2 * g],     ah[0], ah[1], ah[2], ah[3], bl0, bl1);
                mma16816(accS[2 * g + 1], ah[0], ah[1], ah[2], ah[3], bl2, bl3);
                mma16816(accS[2 * g],     al_[0], al_[1], al_[2], al_[3], bh0, bh1);
                mma16816(accS[2 * g + 1], al_[0], al_[1], al_[2], al_[3], bh2, bh3);
            }
        }

#pragma unroll
        for (int j = 0; j < 8; j++) {
            int colL = j * 8 + (lane & 3) * 2;
            int cg = m0 + colL;
            int kv0 = skm_st[colL], kv1 = skm_st[colL + 1];
            float2 gv0 = __half22float2(__ldg((const __half2*)(Grow0 + cg)));
            float2 gv1 = __half22float2(__ldg((const __half2*)(Grow1 + cg)));
            float s00 = fmaf(accS[j][0], SCALE, gv0.x);
            float s01 = fmaf(accS[j][1], SCALE, gv0.y);
            float s10 = fmaf(accS[j][2], SCALE, gv1.x);
            float s11 = fmaf(accS[j][3], SCALE, gv1.y);
            accS[j][0] = rowv0 ? (kv0 ? s00 : -1e30f) : 0.0f;
            accS[j][1] = rowv0 ? (kv1 ? s01 : -1e30f) : 0.0f;
            accS[j][2] = rowv1 ? (kv0 ? s10 : -1e30f) : 0.0f;
            accS[j][3] = rowv1 ? (kv1 ? s11 : -1e30f) : 0.0f;
        }

        float mx0 = -1e30f, mx1 = -1e30f;
#pragma unroll
        for (int j = 0; j < 8; j++) {
            mx0 = fmaxf(mx0, fmaxf(accS[j][0], accS[j][1]));
            mx1 = fmaxf(mx1, fmaxf(accS[j][2], accS[j][3]));
        }
        mx0 = fmaxf(mx0, __shfl_xor_sync(0xffffffffu, mx0, 1));
        mx0 = fmaxf(mx0, __shfl_xor_sync(0xffffffffu, mx0, 2));
        mx1 = fmaxf(mx1, __shfl_xor_sync(0xffffffffu, mx1, 1));
        mx1 = fmaxf(mx1, __shfl_xor_sync(0xffffffffu, mx1, 2));
        float mn0 = fmaxf(mr0, mx0), mn1 = fmaxf(mr1, mx1);
        float al0 = fexp2(mr0 - mn0), al1 = fexp2(mr1 - mn1);
        mr0 = mn0; mr1 = mn1;
        float ls0 = 0.f, ls1 = 0.f;
#pragma unroll
        for (int j = 0; j < 8; j++) {
            accS[j][0] = fexp2(accS[j][0] - mn0);
            accS[j][1] = fexp2(accS[j][1] - mn0);
            accS[j][2] = fexp2(accS[j][2] - mn1);
            accS[j][3] = fexp2(accS[j][3] - mn1);
            ls0 += accS[j][0] + accS[j][1];
            ls1 += accS[j][2] + accS[j][3];
        }
        ls0 += __shfl_xor_sync(0xffffffffu, ls0, 1);
        ls0 += __shfl_xor_sync(0xffffffffu, ls0, 2);
        ls1 += __shfl_xor_sync(0xffffffffu, ls1, 1);
        ls1 += __shfl_xor_sync(0xffffffffu, ls1, 2);
        sr0 = fmaf(sr0, al0, ls0);
        sr1 = fmaf(sr1, al1, ls1);
#pragma unroll
        for (int j = 0; j < 8; j++) {
            accO[j][0] *= al0; accO[j][1] *= al0;
            accO[j][2] *= al1; accO[j][3] *= al1;
        }

#pragma unroll
        for (int tt = 0; tt < 4; tt++) {
            uint32_t ah[4], al_[4];
            pack_hilo(accS[2 * tt][0],     accS[2 * tt][1],     ah[0], al_[0]);
            pack_hilo(accS[2 * tt][2],     accS[2 * tt][3],     ah[1], al_[1]);
            pack_hilo(accS[2 * tt + 1][0], accS[2 * tt + 1][1], ah[2], al_[2]);
            pack_hilo(accS[2 * tt + 1][2], accS[2 * tt + 1][3], ah[3], al_[3]);
            int rb = ((lane >> 4) << 3) + (lane & 7);
            int khb = tt * 2 + ((lane >> 3) & 1);
#pragma unroll
            for (int g = 0; g < 4; g++) {
                int rn = g * 16 + rb;
                uint32_t boff = (uint32_t)(rn * 64 + ((khb ^ (rn & 7)) << 3)) * 2;
                uint32_t bh0, bh1, bh2, bh3, bl0, bl1, bl2, bl3;
                ldsm4(bh0, bh1, bh2, bh3, uVh + boff);
                ldsm4(bl0, bl1, bl2, bl3, uVl + boff);
                mma16816(accO[2 * g],     ah[0], ah[1], ah[2], ah[3], bh0, bh1);
                mma16816(accO[2 * g + 1], ah[0], ah[1], ah[2], ah[3], bh2, bh3);
                mma16816(accO[2 * g],     ah[0], ah[1], ah[2], ah[3], bl0, bl1);
                mma16816(accO[2 * g + 1], ah[0], ah[1], ah[2], ah[3], bl2, bl3);
                mma16816(accO[2 * g],     al_[0], al_[1], al_[2], al_[3], bh0, bh1);
                mma16816(accO[2 * g + 1], al_[0], al_[1], al_[2], al_[3], bh2, bh3);
            }
        }

        __syncthreads();
        if (t + 2 < NTILES) issue_tile(t + 2, st);
        cp_commit();
    }

    float inv0 = __fdividef(1.f, sr0), inv1 = __fdividef(1.f, sr1);
#pragma unroll
    for (int j = 0; j < 8; j++) {
        int d0 = j * 8 + (lane & 3) * 2;
        size_t b0i = (size_t)(b * NN + nr0) * DD + h * HDIM + d0;
        size_t b1i = (size_t)(b * NN + nr1) * DD + h * HDIM + d0;
        uint32_t hi, lo;
        pack_hilo(accO[j][0] * inv0, accO[j][1] * inv0, hi, lo);
        *(uint32_t*)&g_atthi[b0i] = hi;
        *(uint32_t*)&g_attlo[b0i] = lo;
        pack_hilo(accO[j][2] * inv1, accO[j][3] * inv1, hi, lo);
        *(uint32_t*)&g_atthi[b1i] = hi;
        *(uint32_t*)&g_attlo[b1i] = lo;
    }
}

// ---------------- launch ----------------
extern "C" void kernel_launch(void* const* d_in, const int* in_sizes, int n_in,
                              void* d_out, int out_size) {
    const float* x      = (const float*)d_in[0];
    const float* edge   = (const float*)d_in[1];
    const void*  mask   = d_in[2];
    const float* w_qkv  = (const float*)d_in[3];
    const float* w_ep   = (const float*)d_in[4];
    const float* w_eg   = (const float*)d_in[5];
    const float* b_eg   = (const float*)d_in[6];
    const float* w_proj = (const float*)d_in[7];
    const float* b_proj = (const float*)d_in[8];
    float* out = (float*)d_out;

    static bool init_done = false;
    static cudaStream_t s_edge;
    static cudaEvent_t ev_fork, ev_join;
    if (!init_done) {
        cudaFuncSetAttribute(mma_gemm_kernel, cudaFuncAttributeMaxDynamicSharedMemorySize, 65536);
        cudaFuncSetAttribute(attn_kernel, cudaFuncAttributeMaxDynamicSharedMemorySize, 98816);
        cudaStreamCreateWithFlags(&s_edge, cudaStreamNonBlocking);
        cudaEventCreateWithFlags(&ev_fork, cudaEventDisableTiming);
        cudaEventCreateWithFlags(&ev_join, cudaEventDisableTiming);
        init_done = true;
    }

    mask_prep_kernel<<<1, 1024>>>((const unsigned*)mask);

    // fork: edge prep runs on side stream, overlapping cvt + qkv GEMM + vprep
    cudaEventRecord(ev_fork, 0);
    cudaStreamWaitEvent(s_edge, ev_fork, 0);
    dim3 ge(NN / 256, NN, BB);
    edge_prep_kernel<<<ge, 256, 0, s_edge>>>(edge, w_ep, w_eg, b_eg);
    cudaEventRecord(ev_join, s_edge);

    cvt_all_kernel<<<(NX + NW + NP + 255) / 256, 256>>>(x, w_qkv, w_proj);

    dim3 g1(12, 32);
    mma_gemm_kernel<<<g1, 256, 65536>>>(nullptr, nullptr, 0);

    dim3 gv(NTILES, BB * HH);
    vprep_kernel<<<gv, 256>>>();

    // join: attn needs g_G16
    cudaStreamWaitEvent(0, ev_join, 0);

    dim3 ga(NN / QT, HH, BB);
    attn_kernel<<<ga, 256, 98816>>>();

    dim3 g2(4, 32);
    mma_gemm_kernel<<<g2, 256, 65536>>>(b_proj, out, 1);
}

// round 12
// speedup vs baseline: 1.3744x; 1.3744x over previous
#include <cuda_runtime.h>
#include <cuda_bf16.h>
#include <cuda_fp16.h>
#include <cstdint>

#define BB 4
#define NN 1024
#define DD 512
#define HH 8
#define EE 5
#define HDIM 64
#define QT 128
#define KT 64
#define NTILES (NN / KT)
#define L2E 1.4426950408889634f

// ---------------- scratch (device globals; no allocation allowed) ----------------
__device__ float g_v[BB * HH * NN * HDIM];
__device__ int   g_mask[BB * NN];
__device__ int   g_any[BB];
__device__ __half g_G16[(size_t)BB * HH * NN * NN];   // gate*bias*log2e, fp16
__device__ __nv_bfloat16 g_qhi[BB * HH * NN * HDIM], g_qlo[BB * HH * NN * HDIM];
__device__ __nv_bfloat16 g_khi[BB * HH * NN * HDIM], g_klo[BB * HH * NN * HDIM];
__device__ __nv_bfloat16 g_vthi[BB * HH * NN * HDIM], g_vtlo[BB * HH * NN * HDIM];
__device__ __nv_bfloat16 g_xhi[BB * NN * DD],   g_xlo[BB * NN * DD];
__device__ __nv_bfloat16 g_wqkvhi[3 * DD * DD], g_wqkvlo[3 * DD * DD];
__device__ __nv_bfloat16 g_atthi[BB * NN * DD], g_attlo[BB * NN * DD];
__device__ __nv_bfloat16 g_wprojhi[DD * DD],    g_wprojlo[DD * DD];

#define NX (BB * NN * DD)
#define NW (3 * DD * DD)
#define NP (DD * DD)

// ---------------- helpers ----------------
__device__ __forceinline__ uint32_t smem_u32(const void* p) {
    return (uint32_t)__cvta_generic_to_shared(p);
}
__device__ __forceinline__ void ldsm4(uint32_t& r0, uint32_t& r1, uint32_t& r2, uint32_t& r3,
                                      uint32_t a) {
    asm volatile("ldmatrix.sync.aligned.m8n8.x4.shared.b16 {%0,%1,%2,%3}, [%4];"
                 : "=r"(r0), "=r"(r1), "=r"(r2), "=r"(r3) : "r"(a));
}
__device__ __forceinline__ void mma16816(float* c, uint32_t a0, uint32_t a1, uint32_t a2,
                                         uint32_t a3, uint32_t b0, uint32_t b1) {
    asm volatile(
        "mma.sync.aligned.m16n8k16.row.col.f32.bf16.bf16.f32 "
        "{%0,%1,%2,%3}, {%4,%5,%6,%7}, {%8,%9}, {%0,%1,%2,%3};"
        : "+f"(c[0]), "+f"(c[1]), "+f"(c[2]), "+f"(c[3])
        : "r"(a0), "r"(a1), "r"(a2), "r"(a3), "r"(b0), "r"(b1));
}
// .cg: bypass L1 allocation — streamed operands have zero L1 reuse and the
// round-10 profile shows L1TEX (shared port) at 75% as the binding limit.
__device__ __forceinline__ void cp_async16(uint32_t saddr, const void* gaddr) {
    asm volatile("cp.async.cg.shared.global [%0], [%1], 16;" :: "r"(saddr), "l"(gaddr));
}
__device__ __forceinline__ void cp_commit() {
    asm volatile("cp.async.commit_group;" ::: "memory");
}
template <int N>
__device__ __forceinline__ void cp_wait() {
    asm volatile("cp.async.wait_group %0;" :: "n"(N) : "memory");
}
__device__ __forceinline__ float fexp2(float x) {
    float y;
    asm("ex2.approx.ftz.f32 %0, %1;" : "=f"(y) : "f"(x));
    return y;
}
__device__ __forceinline__ void pack_hilo(float p0, float p1, uint32_t& hi, uint32_t& lo) {
    __nv_bfloat16 h0 = __float2bfloat16(p0), h1 = __float2bfloat16(p1);
    hi = ((uint32_t)__bfloat16_as_ushort(h1) << 16) | (uint32_t)__bfloat16_as_ushort(h0);
    __nv_bfloat16 g0 = __float2bfloat16(p0 - __bfloat162float(h0));
    __nv_bfloat16 g1 = __float2bfloat16(p1 - __bfloat162float(h1));
    lo = ((uint32_t)__bfloat16_as_ushort(g1) << 16) | (uint32_t)__bfloat16_as_ushort(g0);
}

// ---------------- kernel 0: mask canonicalization ----------------
__global__ void mask_prep_kernel(const unsigned* __restrict__ mraw) {
    __shared__ int s_int, s_float;
    __shared__ int s_any[BB];
    int t = threadIdx.x;
    if (t == 0) { s_int = 1; s_float = 1; }
    if (t < BB) s_any[t] = 0;
    __syncthreads();
    unsigned v = mraw[t];
    if (v > 1u) atomicAnd(&s_int, 0);
    if (!(v == 0u || v == 0x3F800000u)) atomicAnd(&s_float, 0);
    __syncthreads();
    int mode = s_int ? 0 : (s_float ? 1 : 2);
    for (int i = t; i < BB * NN; i += 1024) {
        int val;
        if (mode == 0)      val = ((const int*)mraw)[i];
        else if (mode == 1) val = (((const unsigned*)mraw)[i] != 0u);
        else                val = ((const unsigned char*)mraw)[i];
        val = val ? 1 : 0;
        g_mask[i] = val;
        if (val) atomicOr(&s_any[i >> 10], 1);
    }
    __syncthreads();
    if (t < BB) g_any[t] = s_any[t];
}

// ---------------- kernel 0b: fused fp32 -> bf16 hi/lo split ----------------
__global__ void cvt_all_kernel(const float* __restrict__ x,
                               const float* __restrict__ wqkv,
                               const float* __restrict__ wproj) {
    int i = blockIdx.x * 256 + threadIdx.x;
    const float* src;
    __nv_bfloat16 *hi, *lo;
    int idx;
    if (i < NX) { src = x; hi = g_xhi; lo = g_xlo; idx = i; }
    else if (i < NX + NW) { src = wqkv; hi = g_wqkvhi; lo = g_wqkvlo; idx = i - NX; }
    else if (i < NX + NW + NP) { src = wproj; hi = g_wprojhi; lo = g_wprojlo; idx = i - NX - NW; }
    else return;
    float v = src[idx];
    __nv_bfloat16 h = __float2bfloat16(v);
    hi[idx] = h;
    lo[idx] = __float2bfloat16(v - __bfloat162float(h));
}

// ---------------- kernel 0c: edge -> G16 = sigmoid(.)*bias*log2e (fp16) ----------------
__global__ __launch_bounds__(256) void edge_prep_kernel(const float* __restrict__ edge,
                                                        const float* __restrict__ w_ep,
                                                        const float* __restrict__ w_eg,
                                                        const float* __restrict__ b_eg) {
    const int m = blockIdx.x * 256 + threadIdx.x;
    const int n = blockIdx.y, b = blockIdx.z;
    const float* ep = edge + ((size_t)(b * NN + n) * NN + m) * EE;
    float e0 = __ldg(ep), e1 = __ldg(ep + 1), e2 = __ldg(ep + 2),
          e3 = __ldg(ep + 3), e4 = __ldg(ep + 4);
#pragma unroll
    for (int h = 0; h < HH; h++) {
        float biasv = e0 * __ldg(&w_ep[h * EE + 0]);
        biasv = fmaf(e1, __ldg(&w_ep[h * EE + 1]), biasv);
        biasv = fmaf(e2, __ldg(&w_ep[h * EE + 2]), biasv);
        biasv = fmaf(e3, __ldg(&w_ep[h * EE + 3]), biasv);
        biasv = fmaf(e4, __ldg(&w_ep[h * EE + 4]), biasv);
        float gv = fmaf(e0, __ldg(&w_eg[h * EE + 0]), __ldg(&b_eg[h]));
        gv = fmaf(e1, __ldg(&w_eg[h * EE + 1]), gv);
        gv = fmaf(e2, __ldg(&w_eg[h * EE + 2]), gv);
        gv = fmaf(e3, __ldg(&w_eg[h * EE + 3]), gv);
        gv = fmaf(e4, __ldg(&w_eg[h * EE + 4]), gv);
        float gate = __fdividef(1.f, 1.f + __expf(-gv));
        g_G16[((size_t)(b * HH + h) * NN + n) * NN + m] = __float2half(gate * biasv * L2E);
    }
}

// ---------------- mma.sync bf16x3 GEMM (round-10 structure, .cg fills) ----------------
__global__ __launch_bounds__(256) void mma_gemm_kernel(const float* __restrict__ bias,
                                                       float* __restrict__ outp, int mode) {
    extern __shared__ __align__(128) char sm[];
    const int tid = threadIdx.x;
    const int wid = tid >> 5, lane = tid & 31;
    const int wm = wid >> 1, wn = wid & 1;
    const int mb = blockIdx.y, cb = blockIdx.x;

    const __nv_bfloat16* Ahi = (mode == 0) ? g_xhi : g_atthi;
    const __nv_bfloat16* Alo = (mode == 0) ? g_xlo : g_attlo;
    const __nv_bfloat16* Bhi = (mode == 0) ? g_wqkvhi : g_wprojhi;
    const __nv_bfloat16* Blo = (mode == 0) ? g_wqkvlo : g_wprojlo;

    const uint32_t sbase = smem_u32(sm);

    int arow[2], axc[2];
#pragma unroll
    for (int mt = 0; mt < 2; mt++) {
        int r = wm * 32 + mt * 16 + (lane & 15);
        arow[mt] = r * 128;
        axc[mt] = r & 7;
    }
    const int akh = lane >> 4;
    int brow[4], bxc[4];
#pragma unroll
    for (int j = 0; j < 4; j++) {
        int r = wn * 64 + j * 16 + ((lane >> 4) << 3) + (lane & 7);
        brow[j] = r * 128;
        bxc[j] = r & 7;
    }
    const int bkh = (lane >> 3) & 1;

    float acc[2][8][4];
#pragma unroll
    for (int mt = 0; mt < 2; mt++)
#pragma unroll
        for (int n8 = 0; n8 < 8; n8++)
#pragma unroll
            for (int q = 0; q < 4; q++) acc[mt][n8][q] = 0.f;

    const int NC = 24;
    auto load_chunk = [&](int c, int stage) {
        int seg = c >> 3, kc = c & 7;
        const __nv_bfloat16* As = (seg == 2) ? Alo : Ahi;
        const __nv_bfloat16* Bs = (seg == 1) ? Blo : Bhi;
        uint32_t st = sbase + stage * 32768;
#pragma unroll
        for (int u8 = 0; u8 < 8; u8++) {
            int u = tid * 8 + u8;
            int isB = u >> 10;
            int uu = u & 1023;
            int r = uu >> 3, ch = uu & 7;
            const __nv_bfloat16* src = isB
                ? (Bs + (size_t)(cb * 128 + r) * DD + kc * 64 + ch * 8)
                : (As + (size_t)(mb * 128 + r) * DD + kc * 64 + ch * 8);
            uint32_t sa = st + isB * 16384 + r * 128 + ((ch ^ (r & 7)) << 4);
            cp_async16(sa, src);
        }
        cp_commit();
    };

    load_chunk(0, 0);
    for (int c = 0; c < NC; c++) {
        if (c + 1 < NC) load_chunk(c + 1, (c + 1) & 1);
        if (c + 1 < NC) cp_wait<1>(); else cp_wait<0>();
        __syncthreads();
        uint32_t sA = sbase + (c & 1) * 32768;
        uint32_t sB = sA + 16384;
#pragma unroll
        for (int k16 = 0; k16 < 4; k16++) {
            uint32_t a[2][4];
#pragma unroll
            for (int mt = 0; mt < 2; mt++) {
                uint32_t ad = sA + arow[mt] + (((k16 * 2 + akh) ^ axc[mt]) << 4);
                ldsm4(a[mt][0], a[mt][1], a[mt][2], a[mt][3], ad);
            }
#pragma unroll
            for (int j = 0; j < 4; j++) {
                uint32_t b0, b1, b2, b3;
                uint32_t bd = sB + brow[j] + (((k16 * 2 + bkh) ^ bxc[j]) << 4);
                ldsm4(b0, b1, b2, b3, bd);
                mma16816(acc[0][2 * j],     a[0][0], a[0][1], a[0][2], a[0][3], b0, b1);
                mma16816(acc[0][2 * j + 1], a[0][0], a[0][1], a[0][2], a[0][3], b2, b3);
                mma16816(acc[1][2 * j],     a[1][0], a[1][1], a[1][2], a[1][3], b0, b1);
                mma16816(acc[1][2 * j + 1], a[1][0], a[1][1], a[1][2], a[1][3], b2, b3);
            }
        }
        __syncthreads();
    }

    const int colw = cb * 128 + wn * 64;
    const int roww = mb * 128 + wm * 32;
#pragma unroll
    for (int mt = 0; mt < 2; mt++) {
#pragma unroll
        for (int n8 = 0; n8 < 8; n8++) {
            int col = colw + n8 * 8 + (lane & 3) * 2;
            int row = roww + mt * 16 + (lane >> 2);
            if (mode == 0) {
                int sect = col >> 9, d = col & 511;
                int h2 = d >> 6, hd = d & 63;
                int b2 = row >> 10, n = row & 1023;
                if (sect < 2) {
                    __nv_bfloat16* dh = (sect == 0) ? g_qhi : g_khi;
                    __nv_bfloat16* dl = (sect == 0) ? g_qlo : g_klo;
                    int ch = (hd >> 3) ^ (row & 7);
                    size_t e0 = ((size_t)(b2 * HH + h2) * NN + n) * HDIM + (ch << 3) + (hd & 7);
                    uint32_t hi, lo;
                    pack_hilo(acc[mt][n8][0], acc[mt][n8][1], hi, lo);
                    *(uint32_t*)&dh[e0] = hi;
                    *(uint32_t*)&dl[e0] = lo;
                    pack_hilo(acc[mt][n8][2], acc[mt][n8][3], hi, lo);
                    *(uint32_t*)&dh[e0 + 8 * HDIM] = hi;
                    *(uint32_t*)&dl[e0 + 8 * HDIM] = lo;
                } else {
                    size_t base = ((size_t)(b2 * HH + h2) * NN + n) * HDIM + hd;
                    *(float2*)&g_v[base] = make_float2(acc[mt][n8][0], acc[mt][n8][1]);
                    *(float2*)&g_v[base + 8 * HDIM] = make_float2(acc[mt][n8][2], acc[mt][n8][3]);
                }
            } else {
                float b0 = bias[col], b1 = bias[col + 1];
                *(float2*)&outp[(size_t)row * DD + col] =
                    make_float2(acc[mt][n8][0] + b0, acc[mt][n8][1] + b1);
                *(float2*)&outp[(size_t)(row + 8) * DD + col] =
                    make_float2(acc[mt][n8][2] + b0, acc[mt][n8][3] + b1);
            }
        }
    }
}

// ---------------- kernel 1b: V transpose -> pre-swizzled bf16 hi/lo tiles ----------------
__global__ __launch_bounds__(256) void vprep_kernel() {
    __shared__ float Vf[64][68];
    const int t = blockIdx.x, bh = blockIdx.y;
    const int tid = threadIdx.x;
    const int m0 = t * KT;
    const float* src = g_v + ((size_t)bh * NN + m0) * HDIM;
    for (int u = tid; u < 1024; u += 256) {
        int key = u >> 4, c4 = (u & 15) * 4;
        *(float4*)&Vf[key][c4] = *(const float4*)(src + key * HDIM + c4);
    }
    __syncthreads();
    __nv_bfloat16* dh = g_vthi + (((size_t)bh * NTILES + t) * 64) * 64;
    __nv_bfloat16* dl = g_vtlo + (((size_t)bh * NTILES + t) * 64) * 64;
    for (int u = tid; u < 1024; u += 256) {
        int d = u >> 4, k4 = (u & 15) * 4;
        uint32_t h0, l0, h1, l1;
        pack_hilo(Vf[k4 + 0][d], Vf[k4 + 1][d], h0, l0);
        pack_hilo(Vf[k4 + 2][d], Vf[k4 + 3][d], h1, l1);
        int chp = (k4 >> 3) ^ (d & 7);
        size_t off = (size_t)d * 64 + (chp << 3) + (k4 & 7);
        *(uint2*)&dh[off] = make_uint2(h0, h1);
        *(uint2*)&dl[off] = make_uint2(l0, l1);
    }
}

// ---------------- kernel 2: tensor-core edge-aware flash attention ----------------
__global__ __launch_bounds__(256, 2) void attn_kernel() {
    extern __shared__ __align__(128) char smraw[];
    const uint32_t sb = smem_u32(smraw);
    const uint32_t uQh = sb, uQl = sb + 16384;
    int* skm = (int*)(smraw + 98304);

    const int b = blockIdx.z, h = blockIdx.y, qt = blockIdx.x;
    const int bh = b * HH + h;
    const int n0 = qt * QT;
    const int tid = threadIdx.x;
    const int lane = tid & 31;
    const int w = tid >> 5;
    const int wq0 = w * 16;
    const float SCALE = 0.125f * L2E;

    const int anyv = g_any[b];

    const __nv_bfloat16* qh = g_qhi + ((size_t)bh * NN + n0) * HDIM;
    const __nv_bfloat16* ql = g_qlo + ((size_t)bh * NN + n0) * HDIM;
    const __nv_bfloat16* kh = g_khi + (size_t)bh * NN * HDIM;
    const __nv_bfloat16* kl = g_klo + (size_t)bh * NN * HDIM;
    const __nv_bfloat16* vh = g_vthi + (size_t)bh * NN * HDIM;
    const __nv_bfloat16* vl = g_vtlo + (size_t)bh * NN * HDIM;

    auto issue_tile = [&](int t, int st) {
        uint32_t base = sb + 32768 + st * 32768;
        size_t ko = (size_t)t * KT * HDIM;
#pragma unroll
        for (int i = 0; i < 2; i++) {
            int u = tid * 2 + i;
            cp_async16(base + u * 16, kh + ko + u * 8);
            cp_async16(base + 8192 + u * 16, kl + ko + u * 8);
            cp_async16(base + 16384 + u * 16, vh + ko + u * 8);
            cp_async16(base + 24576 + u * 16, vl + ko + u * 8);
        }
        if (tid < 16) cp_async16(smem_u32(skm + st * 64) + tid * 16,
                                 g_mask + b * NN + t * KT + tid * 4);
    };

#pragma unroll
    for (int i = 0; i < 4; i++) {
        int u = tid * 4 + i;
        cp_async16(uQh + u * 16, qh + u * 8);
        cp_async16(uQl + u * 16, ql + u * 8);
    }
    issue_tile(0, 0);
    cp_commit();
    issue_tile(1, 1);
    cp_commit();

    const int r_lo = lane >> 2;
    const int nr0 = n0 + wq0 + r_lo;
    const int nr1 = nr0 + 8;
    const int qv0 = g_mask[b * NN + nr0];
    const int qv1 = g_mask[b * NN + nr1];
    const bool rowv0 = qv0 && anyv;
    const bool rowv1 = qv1 && anyv;

    float accO[8][4];
#pragma unroll
    for (int j = 0; j < 8; j++)
#pragma unroll
        for (int q = 0; q < 4; q++) accO[j][q] = 0.f;
    float mr0 = -1e30f, mr1 = -1e30f, sr0 = 0.f, sr1 = 0.f;

    const __half* Grow0 = g_G16 + ((size_t)bh * NN + nr0) * NN;
    const __half* Grow1 = g_G16 + ((size_t)bh * NN + nr1) * NN;

    for (int t = 0; t < NTILES; t++) {
        cp_wait<1>();
        __syncthreads();
        const int st = t & 1;
        const int m0 = t * KT;
        const uint32_t uKh = sb + 32768 + st * 32768;
        const uint32_t uKl = uKh + 8192;
        const uint32_t uVh = uKh + 16384;
        const uint32_t uVl = uKh + 24576;
        const int* skm_st = skm + st * 64;

        float accS[8][4];
#pragma unroll
        for (int j = 0; j < 8; j++)
#pragma unroll
            for (int q = 0; q < 4; q++) accS[j][q] = 0.f;

#pragma unroll
        for (int s = 0; s < 4; s++) {
            int ra = wq0 + (lane & 15);
            int cha = (s * 2 + (lane >> 4)) ^ (ra & 7);
            uint32_t aoff = (uint32_t)(ra * 64 + (cha << 3)) * 2;
            uint32_t ah[4], al_[4];
            ldsm4(ah[0], ah[1], ah[2], ah[3], uQh + aoff);
            ldsm4(al_[0], al_[1], al_[2], al_[3], uQl + aoff);
            int rb = ((lane >> 4) << 3) + (lane & 7);
            int khb = s * 2 + ((lane >> 3) & 1);
#pragma unroll
            for (int g = 0; g < 4; g++) {
                int rn = g * 16 + rb;
                uint32_t boff = (uint32_t)(rn * 64 + ((khb ^ (rn & 7)) << 3)) * 2;
                uint32_t bh0, bh1, bh2, bh3, bl0, bl1, bl2, bl3;
                ldsm4(bh0, bh1, bh2, bh3, uKh + boff);
                ldsm4(bl0, bl1, bl2, bl3, uKl + boff);
                mma16816(accS[2 * g],     ah[0], ah[1], ah[2], ah[3], bh0, bh1);
                mma16816(accS[2 * g + 1], ah[0], ah[1], ah[2], ah[3], bh2, bh3);
                mma16816(accS[2 * g],     ah[0], ah[1], ah[2], ah[3], bl0, bl1);
                mma16816(accS[2 * g + 1], ah[0], ah[1], ah[2], ah[3], bl2, bl3);
                mma16816(accS[2 * g],     al_[0], al_[1], al_[2], al_[3], bh0, bh1);
                mma16816(accS[2 * g + 1], al_[0], al_[1], al_[2], al_[3], bh2, bh3);
            }
        }

#pragma unroll
        for (int j = 0; j < 8; j++) {
            int colL = j * 8 + (lane & 3) * 2;
            int cg = m0 + colL;
            int kv0 = skm_st[colL], kv1 = skm_st[colL + 1];
            float2 gv0 = __half22float2(__ldg((const __half2*)(Grow0 + cg)));
            float2 gv1 = __half22float2(__ldg((const __half2*)(Grow1 + cg)));
            float s00 = fmaf(accS[j][0], SCALE, gv0.x);
            float s01 = fmaf(accS[j][1], SCALE, gv0.y);
            float s10 = fmaf(accS[j][2], SCALE, gv1.x);
            float s11 = fmaf(accS[j][3], SCALE, gv1.y);
            accS[j][0] = rowv0 ? (kv0 ? s00 : -1e30f) : 0.0f;
            accS[j][1] = rowv0 ? (kv1 ? s01 : -1e30f) : 0.0f;
            accS[j][2] = rowv1 ? (kv0 ? s10 : -1e30f) : 0.0f;
            accS[j][3] = rowv1 ? (kv1 ? s11 : -1e30f) : 0.0f;
        }

        float mx0 = -1e30f, mx1 = -1e30f;
#pragma unroll
        for (int j = 0; j < 8; j++) {
            mx0 = fmaxf(mx0, fmaxf(accS[j][0], accS[j][1]));
            mx1 = fmaxf(mx1, fmaxf(accS[j][2], accS[j][3]));
        }
        mx0 = fmaxf(mx0, __shfl_xor_sync(0xffffffffu, mx0, 1));
        mx0 = fmaxf(mx0, __shfl_xor_sync(0xffffffffu, mx0, 2));
        mx1 = fmaxf(mx1, __shfl_xor_sync(0xffffffffu, mx1, 1));
        mx1 = fmaxf(mx1, __shfl_xor_sync(0xffffffffu, mx1, 2));
        float mn0 = fmaxf(mr0, mx0), mn1 = fmaxf(mr1, mx1);
        float al0 = fexp2(mr0 - mn0), al1 = fexp2(mr1 - mn1);
        mr0 = mn0; mr1 = mn1;
        float ls0 = 0.f, ls1 = 0.f;
#pragma unroll
        for (int j = 0; j < 8; j++) {
            accS[j][0] = fexp2(accS[j][0] - mn0);
            accS[j][1] = fexp2(accS[j][1] - mn0);
            accS[j][2] = fexp2(accS[j][2] - mn1);
            accS[j][3] = fexp2(accS[j][3] - mn1);
            ls0 += accS[j][0] + accS[j][1];
            ls1 += accS[j][2] + accS[j][3];
        }
        ls0 += __shfl_xor_sync(0xffffffffu, ls0, 1);
        ls0 += __shfl_xor_sync(0xffffffffu, ls0, 2);
        ls1 += __shfl_xor_sync(0xffffffffu, ls1, 1);
        ls1 += __shfl_xor_sync(0xffffffffu, ls1, 2);
        sr0 = fmaf(sr0, al0, ls0);
        sr1 = fmaf(sr1, al1, ls1);
#pragma unroll
        for (int j = 0; j < 8; j++) {
            accO[j][0] *= al0; accO[j][1] *= al0;
            accO[j][2] *= al1; accO[j][3] *= al1;
        }

#pragma unroll
        for (int tt = 0; tt < 4; tt++) {
            uint32_t ah[4], al_[4];
            pack_hilo(accS[2 * tt][0],     accS[2 * tt][1],     ah[0], al_[0]);
            pack_hilo(accS[2 * tt][2],     accS[2 * tt][3],     ah[1], al_[1]);
            pack_hilo(accS[2 * tt + 1][0], accS[2 * tt + 1][1], ah[2], al_[2]);
            pack_hilo(accS[2 * tt + 1][2], accS[2 * tt + 1][3], ah[3], al_[3]);
            int rb = ((lane >> 4) << 3) + (lane & 7);
            int khb = tt * 2 + ((lane >> 3) & 1);
#pragma unroll
            for (int g = 0; g < 4; g++) {
                int rn = g * 16 + rb;
                uint32_t boff = (uint32_t)(rn * 64 + ((khb ^ (rn & 7)) << 3)) * 2;
                uint32_t bh0, bh1, bh2, bh3, bl0, bl1, bl2, bl3;
                ldsm4(bh0, bh1, bh2, bh3, uVh + boff);
                ldsm4(bl0, bl1, bl2, bl3, uVl + boff);
                mma16816(accO[2 * g],     ah[0], ah[1], ah[2], ah[3], bh0, bh1);
                mma16816(accO[2 * g + 1], ah[0], ah[1], ah[2], ah[3], bh2, bh3);
                mma16816(accO[2 * g],     ah[0], ah[1], ah[2], ah[3], bl0, bl1);
                mma16816(accO[2 * g + 1], ah[0], ah[1], ah[2], ah[3], bl2, bl3);
                mma16816(accO[2 * g],     al_[0], al_[1], al_[2], al_[3], bh0, bh1);
                mma16816(accO[2 * g + 1], al_[0], al_[1], al_[2], al_[3], bh2, bh3);
            }
        }

        __syncthreads();
        if (t + 2 < NTILES) issue_tile(t + 2, st);
        cp_commit();
    }

    float inv0 = __fdividef(1.f, sr0), inv1 = __fdividef(1.f, sr1);
#pragma unroll
    for (int j = 0; j < 8; j++) {
        int d0 = j * 8 + (lane & 3) * 2;
        size_t b0i = (size_t)(b * NN + nr0) * DD + h * HDIM + d0;
        size_t b1i = (size_t)(b * NN + nr1) * DD + h * HDIM + d0;
        uint32_t hi, lo;
        pack_hilo(accO[j][0] * inv0, accO[j][1] * inv0, hi, lo);
        *(uint32_t*)&g_atthi[b0i] = hi;
        *(uint32_t*)&g_attlo[b0i] = lo;
        pack_hilo(accO[j][2] * inv1, accO[j][3] * inv1, hi, lo);
        *(uint32_t*)&g_atthi[b1i] = hi;
        *(uint32_t*)&g_attlo[b1i] = lo;
    }
}

// ---------------- launch ----------------
extern "C" void kernel_launch(void* const* d_in, const int* in_sizes, int n_in,
                              void* d_out, int out_size) {
    const float* x      = (const float*)d_in[0];
    const float* edge   = (const float*)d_in[1];
    const void*  mask   = d_in[2];
    const float* w_qkv  = (const float*)d_in[3];
    const float* w_ep   = (const float*)d_in[4];
    const float* w_eg   = (const float*)d_in[5];
    const float* b_eg   = (const float*)d_in[6];
    const float* w_proj = (const float*)d_in[7];
    const float* b_proj = (const float*)d_in[8];
    float* out = (float*)d_out;

    static bool attr_done = false;
    if (!attr_done) {
        cudaFuncSetAttribute(mma_gemm_kernel, cudaFuncAttributeMaxDynamicSharedMemorySize, 65536);
        cudaFuncSetAttribute(attn_kernel, cudaFuncAttributeMaxDynamicSharedMemorySize, 98816);
        attr_done = true;
    }

    mask_prep_kernel<<<1, 1024>>>((const unsigned*)mask);

    cvt_all_kernel<<<(NX + NW + NP + 255) / 256, 256>>>(x, w_qkv, w_proj);

    dim3 ge(NN / 256, NN, BB);
    edge_prep_kernel<<<ge, 256>>>(edge, w_ep, w_eg, b_eg);

    dim3 g1(12, 32);
    mma_gemm_kernel<<<g1, 256, 65536>>>(nullptr, nullptr, 0);

    dim3 gv(NTILES, BB * HH);
    vprep_kernel<<<gv, 256>>>();

    dim3 ga(NN / QT, HH, BB);
    attn_kernel<<<ga, 256, 98816>>>();

    dim3 g2(4, 32);
    mma_gemm_kernel<<<g2, 256, 65536>>>(b_proj, out, 1);
}

// round 14
// speedup vs baseline: 1.5619x; 1.1364x over previous
#include <cuda_runtime.h>
#include <cuda_bf16.h>
#include <cuda_fp16.h>
#include <cstdint>

#define BB 4
#define NN 1024
#define DD 512
#define HH 8
#define EE 5
#define HDIM 64
#define QT 128
#define KT 64
#define NTILES (NN / KT)
#define L2E 1.4426950408889634f

// ---------------- scratch (device globals; no allocation allowed) ----------------
__device__ float g_v[BB * HH * NN * HDIM];
__device__ int   g_mask[BB * NN];
__device__ int   g_any[BB];
__device__ __half g_G16[(size_t)BB * HH * NN * NN];   // gate*bias*log2e, fp16
// attention operands: fp16 single precision, swizzled layouts
__device__ __half g_q16[BB * HH * NN * HDIM];
__device__ __half g_k16[BB * HH * NN * HDIM];
__device__ __half g_vt16[BB * HH * NN * HDIM];
// bf16 hi/lo splits for GEMMs (bf16x3 error compensation)
__device__ __nv_bfloat16 g_xhi[BB * NN * DD],   g_xlo[BB * NN * DD];
__device__ __nv_bfloat16 g_wqkvhi[3 * DD * DD], g_wqkvlo[3 * DD * DD];
__device__ __nv_bfloat16 g_atthi[BB * NN * DD], g_attlo[BB * NN * DD];
__device__ __nv_bfloat16 g_wprojhi[DD * DD],    g_wprojlo[DD * DD];

#define NX (BB * NN * DD)
#define NW (3 * DD * DD)
#define NP (DD * DD)

// ---------------- helpers ----------------
__device__ __forceinline__ uint32_t smem_u32(const void* p) {
    return (uint32_t)__cvta_generic_to_shared(p);
}
__device__ __forceinline__ void ldsm4(uint32_t& r0, uint32_t& r1, uint32_t& r2, uint32_t& r3,
                                      uint32_t a) {
    asm volatile("ldmatrix.sync.aligned.m8n8.x4.shared.b16 {%0,%1,%2,%3}, [%4];"
                 : "=r"(r0), "=r"(r1), "=r"(r2), "=r"(r3) : "r"(a));
}
__device__ __forceinline__ void mma16816(float* c, uint32_t a0, uint32_t a1, uint32_t a2,
                                         uint32_t a3, uint32_t b0, uint32_t b1) {
    asm volatile(
        "mma.sync.aligned.m16n8k16.row.col.f32.bf16.bf16.f32 "
        "{%0,%1,%2,%3}, {%4,%5,%6,%7}, {%8,%9}, {%0,%1,%2,%3};"
        : "+f"(c[0]), "+f"(c[1]), "+f"(c[2]), "+f"(c[3])
        : "r"(a0), "r"(a1), "r"(a2), "r"(a3), "r"(b0), "r"(b1));
}
__device__ __forceinline__ void mma16816h(float* c, uint32_t a0, uint32_t a1, uint32_t a2,
                                          uint32_t a3, uint32_t b0, uint32_t b1) {
    asm volatile(
        "mma.sync.aligned.m16n8k16.row.col.f32.f16.f16.f32 "
        "{%0,%1,%2,%3}, {%4,%5,%6,%7}, {%8,%9}, {%0,%1,%2,%3};"
        : "+f"(c[0]), "+f"(c[1]), "+f"(c[2]), "+f"(c[3])
        : "r"(a0), "r"(a1), "r"(a2), "r"(a3), "r"(b0), "r"(b1));
}
__device__ __forceinline__ void cp_async16(uint32_t saddr, const void* gaddr) {
    asm volatile("cp.async.cg.shared.global [%0], [%1], 16;" :: "r"(saddr), "l"(gaddr));
}
__device__ __forceinline__ void cp_commit() {
    asm volatile("cp.async.commit_group;" ::: "memory");
}
template <int N>
__device__ __forceinline__ void cp_wait() {
    asm volatile("cp.async.wait_group %0;" :: "n"(N) : "memory");
}
__device__ __forceinline__ float fexp2(float x) {
    float y;
    asm("ex2.approx.ftz.f32 %0, %1;" : "=f"(y) : "f"(x));
    return y;
}
__device__ __forceinline__ void pack_hilo(float p0, float p1, uint32_t& hi, uint32_t& lo) {
    __nv_bfloat16 h0 = __float2bfloat16(p0), h1 = __float2bfloat16(p1);
    hi = ((uint32_t)__bfloat16_as_ushort(h1) << 16) | (uint32_t)__bfloat16_as_ushort(h0);
    __nv_bfloat16 g0 = __float2bfloat16(p0 - __bfloat162float(h0));
    __nv_bfloat16 g1 = __float2bfloat16(p1 - __bfloat162float(h1));
    lo = ((uint32_t)__bfloat16_as_ushort(g1) << 16) | (uint32_t)__bfloat16_as_ushort(g0);
}
__device__ __forceinline__ uint32_t pack_h2(float p0, float p1) {
    __half2 hv = __floats2half2_rn(p0, p1);   // p0 -> low 16 bits
    return *(uint32_t*)&hv;
}

// ---------------- kernel 0: mask canonicalization ----------------
__global__ void mask_prep_kernel(const unsigned* __restrict__ mraw) {
    __shared__ int s_int, s_float;
    __shared__ int s_any[BB];
    int t = threadIdx.x;
    if (t == 0) { s_int = 1; s_float = 1; }
    if (t < BB) s_any[t] = 0;
    __syncthreads();
    unsigned v = mraw[t];
    if (v > 1u) atomicAnd(&s_int, 0);
    if (!(v == 0u || v == 0x3F800000u)) atomicAnd(&s_float, 0);
    __syncthreads();
    int mode = s_int ? 0 : (s_float ? 1 : 2);
    for (int i = t; i < BB * NN; i += 1024) {
        int val;
        if (mode == 0)      val = ((const int*)mraw)[i];
        else if (mode == 1) val = (((const unsigned*)mraw)[i] != 0u);
        else                val = ((const unsigned char*)mraw)[i];
        val = val ? 1 : 0;
        g_mask[i] = val;
        if (val) atomicOr(&s_any[i >> 10], 1);
    }
    __syncthreads();
    if (t < BB) g_any[t] = s_any[t];
}

// ---------------- kernel 0b: fused fp32 -> bf16 hi/lo split ----------------
__global__ void cvt_all_kernel(const float* __restrict__ x,
                               const float* __restrict__ wqkv,
                               const float* __restrict__ wproj) {
    int i = blockIdx.x * 256 + threadIdx.x;
    const float* src;
    __nv_bfloat16 *hi, *lo;
    int idx;
    if (i < NX) { src = x; hi = g_xhi; lo = g_xlo; idx = i; }
    else if (i < NX + NW) { src = wqkv; hi = g_wqkvhi; lo = g_wqkvlo; idx = i - NX; }
    else if (i < NX + NW + NP) { src = wproj; hi = g_wprojhi; lo = g_wprojlo; idx = i - NX - NW; }
    else return;
    float v = src[idx];
    __nv_bfloat16 h = __float2bfloat16(v);
    hi[idx] = h;
    lo[idx] = __float2bfloat16(v - __bfloat162float(h));
}

// ---------------- kernel 0c: edge -> G16 = sigmoid(.)*bias*log2e (fp16) ----------------
__global__ __launch_bounds__(256) void edge_prep_kernel(const float* __restrict__ edge,
                                                        const float* __restrict__ w_ep,
                                                        const float* __restrict__ w_eg,
                                                        const float* __restrict__ b_eg) {
    const int m = blockIdx.x * 256 + threadIdx.x;
    const int n = blockIdx.y, b = blockIdx.z;
    const float* ep = edge + ((size_t)(b * NN + n) * NN + m) * EE;
    float e0 = __ldg(ep), e1 = __ldg(ep + 1), e2 = __ldg(ep + 2),
          e3 = __ldg(ep + 3), e4 = __ldg(ep + 4);
#pragma unroll
    for (int h = 0; h < HH; h++) {
        float biasv = e0 * __ldg(&w_ep[h * EE + 0]);
        biasv = fmaf(e1, __ldg(&w_ep[h * EE + 1]), biasv);
        biasv = fmaf(e2, __ldg(&w_ep[h * EE + 2]), biasv);
        biasv = fmaf(e3, __ldg(&w_ep[h * EE + 3]), biasv);
        biasv = fmaf(e4, __ldg(&w_ep[h * EE + 4]), biasv);
        float gv = fmaf(e0, __ldg(&w_eg[h * EE + 0]), __ldg(&b_eg[h]));
        gv = fmaf(e1, __ldg(&w_eg[h * EE + 1]), gv);
        gv = fmaf(e2, __ldg(&w_eg[h * EE + 2]), gv);
        gv = fmaf(e3, __ldg(&w_eg[h * EE + 3]), gv);
        gv = fmaf(e4, __ldg(&w_eg[h * EE + 4]), gv);
        float gate = __fdividef(1.f, 1.f + __expf(-gv));
        g_G16[((size_t)(b * HH + h) * NN + n) * NN + m] = __float2half(gate * biasv * L2E);
    }
}

// ---------------- mma.sync bf16x3 GEMM (round-12 core; Q/K emitted fp16) ----------------
__global__ __launch_bounds__(256) void mma_gemm_kernel(const float* __restrict__ bias,
                                                       float* __restrict__ outp, int mode) {
    extern __shared__ __align__(128) char sm[];
    const int tid = threadIdx.x;
    const int wid = tid >> 5, lane = tid & 31;
    const int wm = wid >> 1, wn = wid & 1;
    const int mb = blockIdx.y, cb = blockIdx.x;

    const __nv_bfloat16* Ahi = (mode == 0) ? g_xhi : g_atthi;
    const __nv_bfloat16* Alo = (mode == 0) ? g_xlo : g_attlo;
    const __nv_bfloat16* Bhi = (mode == 0) ? g_wqkvhi : g_wprojhi;
    const __nv_bfloat16* Blo = (mode == 0) ? g_wqkvlo : g_wprojlo;

    const uint32_t sbase = smem_u32(sm);

    int arow[2], axc[2];
#pragma unroll
    for (int mt = 0; mt < 2; mt++) {
        int r = wm * 32 + mt * 16 + (lane & 15);
        arow[mt] = r * 128;
        axc[mt] = r & 7;
    }
    const int akh = lane >> 4;
    int brow[4], bxc[4];
#pragma unroll
    for (int j = 0; j < 4; j++) {
        int r = wn * 64 + j * 16 + ((lane >> 4) << 3) + (lane & 7);
        brow[j] = r * 128;
        bxc[j] = r & 7;
    }
    const int bkh = (lane >> 3) & 1;

    float acc[2][8][4];
#pragma unroll
    for (int mt = 0; mt < 2; mt++)
#pragma unroll
        for (int n8 = 0; n8 < 8; n8++)
#pragma unroll
            for (int q = 0; q < 4; q++) acc[mt][n8][q] = 0.f;

    const int NC = 24;
    auto load_chunk = [&](int c, int stage) {
        int seg = c >> 3, kc = c & 7;
        const __nv_bfloat16* As = (seg == 2) ? Alo : Ahi;
        const __nv_bfloat16* Bs = (seg == 1) ? Blo : Bhi;
        uint32_t st = sbase + stage * 32768;
#pragma unroll
        for (int u8 = 0; u8 < 8; u8++) {
            int u = tid * 8 + u8;
            int isB = u >> 10;
            int uu = u & 1023;
            int r = uu >> 3, ch = uu & 7;
            const __nv_bfloat16* src = isB
                ? (Bs + (size_t)(cb * 128 + r) * DD + kc * 64 + ch * 8)
                : (As + (size_t)(mb * 128 + r) * DD + kc * 64 + ch * 8);
            uint32_t sa = st + isB * 16384 + r * 128 + ((ch ^ (r & 7)) << 4);
            cp_async16(sa, src);
        }
        cp_commit();
    };

    load_chunk(0, 0);
    for (int c = 0; c < NC; c++) {
        if (c + 1 < NC) load_chunk(c + 1, (c + 1) & 1);
        if (c + 1 < NC) cp_wait<1>(); else cp_wait<0>();
        __syncthreads();
        uint32_t sA = sbase + (c & 1) * 32768;
        uint32_t sB = sA + 16384;
#pragma unroll
        for (int k16 = 0; k16 < 4; k16++) {
            uint32_t a[2][4];
#pragma unroll
            for (int mt = 0; mt < 2; mt++) {
                uint32_t ad = sA + arow[mt] + (((k16 * 2 + akh) ^ axc[mt]) << 4);
                ldsm4(a[mt][0], a[mt][1], a[mt][2], a[mt][3], ad);
            }
#pragma unroll
            for (int j = 0; j < 4; j++) {
                uint32_t b0, b1, b2, b3;
                uint32_t bd = sB + brow[j] + (((k16 * 2 + bkh) ^ bxc[j]) << 4);
                ldsm4(b0, b1, b2, b3, bd);
                mma16816(acc[0][2 * j],     a[0][0], a[0][1], a[0][2], a[0][3], b0, b1);
                mma16816(acc[0][2 * j + 1], a[0][0], a[0][1], a[0][2], a[0][3], b2, b3);
                mma16816(acc[1][2 * j],     a[1][0], a[1][1], a[1][2], a[1][3], b0, b1);
                mma16816(acc[1][2 * j + 1], a[1][0], a[1][1], a[1][2], a[1][3], b2, b3);
            }
        }
        __syncthreads();
    }

    const int colw = cb * 128 + wn * 64;
    const int roww = mb * 128 + wm * 32;
#pragma unroll
    for (int mt = 0; mt < 2; mt++) {
#pragma unroll
        for (int n8 = 0; n8 < 8; n8++) {
            int col = colw + n8 * 8 + (lane & 3) * 2;
            int row = roww + mt * 16 + (lane >> 2);
            if (mode == 0) {
                int sect = col >> 9, d = col & 511;
                int h2 = d >> 6, hd = d & 63;
                int b2 = row >> 10, n = row & 1023;
                if (sect < 2) {
                    // Q/K: swizzled fp16 single (attention runs an fp16 pipeline)
                    __half* dst = (sect == 0) ? g_q16 : g_k16;
                    int ch = (hd >> 3) ^ (row & 7);
                    size_t e0 = ((size_t)(b2 * HH + h2) * NN + n) * HDIM + (ch << 3) + (hd & 7);
                    *(uint32_t*)&dst[e0] = pack_h2(acc[mt][n8][0], acc[mt][n8][1]);
                    *(uint32_t*)&dst[e0 + 8 * HDIM] = pack_h2(acc[mt][n8][2], acc[mt][n8][3]);
                } else {
                    size_t base = ((size_t)(b2 * HH + h2) * NN + n) * HDIM + hd;
                    *(float2*)&g_v[base] = make_float2(acc[mt][n8][0], acc[mt][n8][1]);
                    *(float2*)&g_v[base + 8 * HDIM] = make_float2(acc[mt][n8][2], acc[mt][n8][3]);
                }
            } else {
                float b0 = bias[col], b1 = bias[col + 1];
                *(float2*)&outp[(size_t)row * DD + col] =
                    make_float2(acc[mt][n8][0] + b0, acc[mt][n8][1] + b1);
                *(float2*)&outp[(size_t)(row + 8) * DD + col] =
                    make_float2(acc[mt][n8][2] + b0, acc[mt][n8][3] + b1);
            }
        }
    }
}

// ---------------- kernel 1b: V transpose -> pre-swizzled fp16 tiles ----------------
__global__ __launch_bounds__(256) void vprep_kernel() {
    __shared__ float Vf[64][68];
    const int t = blockIdx.x, bh = blockIdx.y;
    const int tid = threadIdx.x;
    const int m0 = t * KT;
    const float* src = g_v + ((size_t)bh * NN + m0) * HDIM;
    for (int u = tid; u < 1024; u += 256) {
        int key = u >> 4, c4 = (u & 15) * 4;
        *(float4*)&Vf[key][c4] = *(const float4*)(src + key * HDIM + c4);
    }
    __syncthreads();
    __half* dh = g_vt16 + (((size_t)bh * NTILES + t) * 64) * 64;
    for (int u = tid; u < 1024; u += 256) {
        int d = u >> 4, k4 = (u & 15) * 4;
        uint32_t h0 = pack_h2(Vf[k4 + 0][d], Vf[k4 + 1][d]);
        uint32_t h1 = pack_h2(Vf[k4 + 2][d], Vf[k4 + 3][d]);
        int chp = (k4 >> 3) ^ (d & 7);
        size_t off = (size_t)d * 64 + (chp << 3) + (k4 & 7);
        *(uint2*)&dh[off] = make_uint2(h0, h1);
    }
}

// ---------------- kernel 2: fp16 tensor-core edge-aware flash attention ----------------
// Q/K/V/P all fp16 single (calibrated error ~3e-4 << 1e-3 gate).
// smem: Q 16K | stage0 {K 8K, V 8K} | stage1 {K 8K, V 8K} | masks.
__global__ __launch_bounds__(256, 2) void attn_kernel() {
    extern __shared__ __align__(128) char smraw[];
    const uint32_t sb = smem_u32(smraw);
    const uint32_t uQ = sb;
    int* skm = (int*)(smraw + 49152);

    const int b = blockIdx.z, h = blockIdx.y, qt = blockIdx.x;
    const int bh = b * HH + h;
    const int n0 = qt * QT;
    const int tid = threadIdx.x;
    const int lane = tid & 31;
    const int w = tid >> 5;
    const int wq0 = w * 16;
    const float SCALE = 0.125f * L2E;

    const int anyv = g_any[b];

    const __half* q16 = g_q16 + ((size_t)bh * NN + n0) * HDIM;
    const __half* k16 = g_k16 + (size_t)bh * NN * HDIM;
    const __half* v16 = g_vt16 + (size_t)bh * NN * HDIM;

    auto issue_tile = [&](int t, int st) {
        uint32_t base = sb + 16384 + st * 16384;
        size_t ko = (size_t)t * KT * HDIM;
#pragma unroll
        for (int i = 0; i < 2; i++) {
            int u = tid * 2 + i;           // 0..511 16B units per matrix
            cp_async16(base + u * 16, k16 + ko + u * 8);
            cp_async16(base + 8192 + u * 16, v16 + ko + u * 8);
        }
        if (tid < 16) cp_async16(smem_u32(skm + st * 64) + tid * 16,
                                 g_mask + b * NN + t * KT + tid * 4);
    };

#pragma unroll
    for (int i = 0; i < 4; i++) {
        int u = tid * 4 + i;               // 0..1023 16B units (Q 16KB)
        cp_async16(uQ + u * 16, q16 + u * 8);
    }
    issue_tile(0, 0);
    cp_commit();
    issue_tile(1, 1);
    cp_commit();

    const int r_lo = lane >> 2;
    const int nr0 = n0 + wq0 + r_lo;
    const int nr1 = nr0 + 8;
    const int qv0 = g_mask[b * NN + nr0];
    const int qv1 = g_mask[b * NN + nr1];
    const bool rowv0 = qv0 && anyv;
    const bool rowv1 = qv1 && anyv;

    float accO[8][4];
#pragma unroll
    for (int j = 0; j < 8; j++)
#pragma unroll
        for (int q = 0; q < 4; q++) accO[j][q] = 0.f;
    float mr0 = -1e30f, mr1 = -1e30f, sr0 = 0.f, sr1 = 0.f;

    const __half* Grow0 = g_G16 + ((size_t)bh * NN + nr0) * NN;
    const __half* Grow1 = g_G16 + ((size_t)bh * NN + nr1) * NN;

    for (int t = 0; t < NTILES; t++) {
        cp_wait<1>();
        __syncthreads();
        const int st = t & 1;
        const int m0 = t * KT;
        const uint32_t uK = sb + 16384 + st * 16384;
        const uint32_t uV = uK + 8192;
        const int* skm_st = skm + st * 64;

        // ---- S = Q K^T (fp16 single) ----
        float accS[8][4];
#pragma unroll
        for (int j = 0; j < 8; j++)
#pragma unroll
            for (int q = 0; q < 4; q++) accS[j][q] = 0.f;

#pragma unroll
        for (int s = 0; s < 4; s++) {
            int ra = wq0 + (lane & 15);
            int cha = (s * 2 + (lane >> 4)) ^ (ra & 7);
            uint32_t aoff = (uint32_t)(ra * 64 + (cha << 3)) * 2;
            uint32_t ah0, ah1, ah2, ah3;
            ldsm4(ah0, ah1, ah2, ah3, uQ + aoff);
            int rb = ((lane >> 4) << 3) + (lane & 7);
            int khb = s * 2 + ((lane >> 3) & 1);
#pragma unroll
            for (int g = 0; g < 4; g++) {
                int rn = g * 16 + rb;
                uint32_t boff = (uint32_t)(rn * 64 + ((khb ^ (rn & 7)) << 3)) * 2;
                uint32_t bh0, bh1, bh2, bh3;
                ldsm4(bh0, bh1, bh2, bh3, uK + boff);
                mma16816h(accS[2 * g],     ah0, ah1, ah2, ah3, bh0, bh1);
                mma16816h(accS[2 * g + 1], ah0, ah1, ah2, ah3, bh2, bh3);
            }
        }

        // ---- epilogue: scale(log2 domain) + fp16 G + mask ----
#pragma unroll
        for (int j = 0; j < 8; j++) {
            int colL = j * 8 + (lane & 3) * 2;
            int cg = m0 + colL;
            int kv0 = skm_st[colL], kv1 = skm_st[colL + 1];
            float2 gv0 = __half22float2(__ldg((const __half2*)(Grow0 + cg)));
            float2 gv1 = __half22float2(__ldg((const __half2*)(Grow1 + cg)));
            float s00 = fmaf(accS[j][0], SCALE, gv0.x);
            float s01 = fmaf(accS[j][1], SCALE, gv0.y);
            float s10 = fmaf(accS[j][2], SCALE, gv1.x);
            float s11 = fmaf(accS[j][3], SCALE, gv1.y);
            accS[j][0] = rowv0 ? (kv0 ? s00 : -1e30f) : 0.0f;
            accS[j][1] = rowv0 ? (kv1 ? s01 : -1e30f) : 0.0f;
            accS[j][2] = rowv1 ? (kv0 ? s10 : -1e30f) : 0.0f;
            accS[j][3] = rowv1 ? (kv1 ? s11 : -1e30f) : 0.0f;
        }

        // ---- online softmax (exp2 domain) ----
        float mx0 = -1e30f, mx1 = -1e30f;
#pragma unroll
        for (int j = 0; j < 8; j++) {
            mx0 = fmaxf(mx0, fmaxf(accS[j][0], accS[j][1]));
            mx1 = fmaxf(mx1, fmaxf(accS[j][2], accS[j][3]));
        }
        mx0 = fmaxf(mx0, __shfl_xor_sync(0xffffffffu, mx0, 1));
        mx0 = fmaxf(mx0, __shfl_xor_sync(0xffffffffu, mx0, 2));
        mx1 = fmaxf(mx1, __shfl_xor_sync(0xffffffffu, mx1, 1));
        mx1 = fmaxf(mx1, __shfl_xor_sync(0xffffffffu, mx1, 2));
        float mn0 = fmaxf(mr0, mx0), mn1 = fmaxf(mr1, mx1);
        float al0 = fexp2(mr0 - mn0), al1 = fexp2(mr1 - mn1);
        mr0 = mn0; mr1 = mn1;
        float ls0 = 0.f, ls1 = 0.f;
#pragma unroll
        for (int j = 0; j < 8; j++) {
            accS[j][0] = fexp2(accS[j][0] - mn0);
            accS[j][1] = fexp2(accS[j][1] - mn0);
            accS[j][2] = fexp2(accS[j][2] - mn1);
            accS[j][3] = fexp2(accS[j][3] - mn1);
            ls0 += accS[j][0] + accS[j][1];
            ls1 += accS[j][2] + accS[j][3];
        }
        ls0 += __shfl_xor_sync(0xffffffffu, ls0, 1);
        ls0 += __shfl_xor_sync(0xffffffffu, ls0, 2);
        ls1 += __shfl_xor_sync(0xffffffffu, ls1, 1);
        ls1 += __shfl_xor_sync(0xffffffffu, ls1, 2);
        sr0 = fmaf(sr0, al0, ls0);
        sr1 = fmaf(sr1, al1, ls1);
#pragma unroll
        for (int j = 0; j < 8; j++) {
            accO[j][0] *= al0; accO[j][1] *= al0;
            accO[j][2] *= al1; accO[j][3] *= al1;
        }

        // ---- O += P V (fp16 single) ----
#pragma unroll
        for (int tt = 0; tt < 4; tt++) {
            uint32_t ah0 = pack_h2(accS[2 * tt][0],     accS[2 * tt][1]);
            uint32_t ah1 = pack_h2(accS[2 * tt][2],     accS[2 * tt][3]);
            uint32_t ah2 = pack_h2(accS[2 * tt + 1][0], accS[2 * tt + 1][1]);
            uint32_t ah3 = pack_h2(accS[2 * tt + 1][2], accS[2 * tt + 1][3]);
            int rb = ((lane >> 4) << 3) + (lane & 7);
            int khb = tt * 2 + ((lane >> 3) & 1);
#pragma unroll
            for (int g = 0; g < 4; g++) {
                int rn = g * 16 + rb;
                uint32_t boff = (uint32_t)(rn * 64 + ((khb ^ (rn & 7)) << 3)) * 2;
                uint32_t bh0, bh1, bh2, bh3;
                ldsm4(bh0, bh1, bh2, bh3, uV + boff);
                mma16816h(accO[2 * g],     ah0, ah1, ah2, ah3, bh0, bh1);
                mma16816h(accO[2 * g + 1], ah0, ah1, ah2, ah3, bh2, bh3);
            }
        }

        __syncthreads();
        if (t + 2 < NTILES) issue_tile(t + 2, st);
        cp_commit();
    }

    // ---- final: normalize + emit bf16 hi/lo for proj GEMM ----
    float inv0 = __fdividef(1.f, sr0), inv1 = __fdividef(1.f, sr1);
#pragma unroll
    for (int j = 0; j < 8; j++) {
        int d0 = j * 8 + (lane & 3) * 2;
        size_t b0i = (size_t)(b * NN + nr0) * DD + h * HDIM + d0;
        size_t b1i = (size_t)(b * NN + nr1) * DD + h * HDIM + d0;
        uint32_t hi, lo;
        pack_hilo(accO[j][0] * inv0, accO[j][1] * inv0, hi, lo);
        *(uint32_t*)&g_atthi[b0i] = hi;
        *(uint32_t*)&g_attlo[b0i] = lo;
        pack_hilo(accO[j][2] * inv1, accO[j][3] * inv1, hi, lo);
        *(uint32_t*)&g_atthi[b1i] = hi;
        *(uint32_t*)&g_attlo[b1i] = lo;
    }
}

// ---------------- launch ----------------
extern "C" void kernel_launch(void* const* d_in, const int* in_sizes, int n_in,
                              void* d_out, int out_size) {
    const float* x      = (const float*)d_in[0];
    const float* edge   = (const float*)d_in[1];
    const void*  mask   = d_in[2];
    const float* w_qkv  = (const float*)d_in[3];
    const float* w_ep   = (const float*)d_in[4];
    const float* w_eg   = (const float*)d_in[5];
    const float* b_eg   = (const float*)d_in[6];
    const float* w_proj = (const float*)d_in[7];
    const float* b_proj = (const float*)d_in[8];
    float* out = (float*)d_out;

    static bool attr_done = false;
    if (!attr_done) {
        cudaFuncSetAttribute(mma_gemm_kernel, cudaFuncAttributeMaxDynamicSharedMemorySize, 65536);
        cudaFuncSetAttribute(attn_kernel, cudaFuncAttributeMaxDynamicSharedMemorySize, 49664);
        attr_done = true;
    }

    mask_prep_kernel<<<1, 1024>>>((const unsigned*)mask);

    cvt_all_kernel<<<(NX + NW + NP + 255) / 256, 256>>>(x, w_qkv, w_proj);

    dim3 ge(NN / 256, NN, BB);
    edge_prep_kernel<<<ge, 256>>>(edge, w_ep, w_eg, b_eg);

    dim3 g1(12, 32);
    mma_gemm_kernel<<<g1, 256, 65536>>>(nullptr, nullptr, 0);

    dim3 gv(NTILES, BB * HH);
    vprep_kernel<<<gv, 256>>>();

    dim3 ga(NN / QT, HH, BB);
    attn_kernel<<<ga, 256, 49664>>>();

    dim3 g2(4, 32);
    mma_gemm_kernel<<<g2, 256, 65536>>>(b_proj, out, 1);
}

// round 15
// speedup vs baseline: 1.9053x; 1.2199x over previous
#include <cuda_runtime.h>
#include <cuda_bf16.h>
#include <cuda_fp16.h>
#include <cstdint>

#define BB 4
#define NN 1024
#define DD 512
#define HH 8
#define EE 5
#define HDIM 64
#define QT 128
#define KT 64
#define NTILES (NN / KT)
#define L2E 1.4426950408889634f

// ---------------- scratch (device globals; no allocation allowed) ----------------
__device__ float g_v[BB * HH * NN * HDIM];
__device__ int   g_mask[BB * NN];
__device__ int   g_any[BB];
__device__ __half g_G16[(size_t)BB * HH * NN * NN];   // gate*bias*log2e, fp16
// attention operands: fp16 single, swizzled layouts
__device__ __half g_q16[BB * HH * NN * HDIM];
__device__ __half g_k16[BB * HH * NN * HDIM];
__device__ __half g_vt16[BB * HH * NN * HDIM];
// fp16x2 GEMM operands: A split hi/lo (exact), B single-rounded
__device__ __half g_x16h[BB * NN * DD],  g_x16l[BB * NN * DD];
__device__ __half g_wqkv16[3 * DD * DD];
__device__ __half g_att16h[BB * NN * DD], g_att16l[BB * NN * DD];
__device__ __half g_wproj16[DD * DD];

#define NX (BB * NN * DD)
#define NW (3 * DD * DD)
#define NP (DD * DD)

// ---------------- helpers ----------------
__device__ __forceinline__ uint32_t smem_u32(const void* p) {
    return (uint32_t)__cvta_generic_to_shared(p);
}
__device__ __forceinline__ void ldsm4(uint32_t& r0, uint32_t& r1, uint32_t& r2, uint32_t& r3,
                                      uint32_t a) {
    asm volatile("ldmatrix.sync.aligned.m8n8.x4.shared.b16 {%0,%1,%2,%3}, [%4];"
                 : "=r"(r0), "=r"(r1), "=r"(r2), "=r"(r3) : "r"(a));
}
__device__ __forceinline__ void mma16816h(float* c, uint32_t a0, uint32_t a1, uint32_t a2,
                                          uint32_t a3, uint32_t b0, uint32_t b1) {
    asm volatile(
        "mma.sync.aligned.m16n8k16.row.col.f32.f16.f16.f32 "
        "{%0,%1,%2,%3}, {%4,%5,%6,%7}, {%8,%9}, {%0,%1,%2,%3};"
        : "+f"(c[0]), "+f"(c[1]), "+f"(c[2]), "+f"(c[3])
        : "r"(a0), "r"(a1), "r"(a2), "r"(a3), "r"(b0), "r"(b1));
}
__device__ __forceinline__ void cp_async16(uint32_t saddr, const void* gaddr) {
    asm volatile("cp.async.cg.shared.global [%0], [%1], 16;" :: "r"(saddr), "l"(gaddr));
}
__device__ __forceinline__ void cp_commit() {
    asm volatile("cp.async.commit_group;" ::: "memory");
}
template <int N>
__device__ __forceinline__ void cp_wait() {
    asm volatile("cp.async.wait_group %0;" :: "n"(N) : "memory");
}
__device__ __forceinline__ float fexp2(float x) {
    float y;
    asm("ex2.approx.ftz.f32 %0, %1;" : "=f"(y) : "f"(x));
    return y;
}
__device__ __forceinline__ uint32_t pack_h2(float p0, float p1) {
    __half2 hv = __floats2half2_rn(p0, p1);   // p0 -> low 16 bits
    return *(uint32_t*)&hv;
}
__device__ __forceinline__ void pack_hilo16(float p0, float p1, uint32_t& hi, uint32_t& lo) {
    __half h0 = __float2half_rn(p0), h1 = __float2half_rn(p1);
    __half2 hv; hv.x = h0; hv.y = h1;
    hi = *(uint32_t*)&hv;
    __half l0 = __float2half_rn(p0 - __half2float(h0));
    __half l1 = __float2half_rn(p1 - __half2float(h1));
    __half2 lv; lv.x = l0; lv.y = l1;
    lo = *(uint32_t*)&lv;
}

// ---------------- kernel 0: mask canonicalization ----------------
__global__ void mask_prep_kernel(const unsigned* __restrict__ mraw) {
    __shared__ int s_int, s_float;
    __shared__ int s_any[BB];
    int t = threadIdx.x;
    if (t == 0) { s_int = 1; s_float = 1; }
    if (t < BB) s_any[t] = 0;
    __syncthreads();
    unsigned v = mraw[t];
    if (v > 1u) atomicAnd(&s_int, 0);
    if (!(v == 0u || v == 0x3F800000u)) atomicAnd(&s_float, 0);
    __syncthreads();
    int mode = s_int ? 0 : (s_float ? 1 : 2);
    for (int i = t; i < BB * NN; i += 1024) {
        int val;
        if (mode == 0)      val = ((const int*)mraw)[i];
        else if (mode == 1) val = (((const unsigned*)mraw)[i] != 0u);
        else                val = ((const unsigned char*)mraw)[i];
        val = val ? 1 : 0;
        g_mask[i] = val;
        if (val) atomicOr(&s_any[i >> 10], 1);
    }
    __syncthreads();
    if (t < BB) g_any[t] = s_any[t];
}

// ---------------- kernel 0b: fp32 -> fp16 prep (x hi/lo, weights single) ----------------
__global__ void cvt_all_kernel(const float* __restrict__ x,
                               const float* __restrict__ wqkv,
                               const float* __restrict__ wproj) {
    int i = blockIdx.x * 256 + threadIdx.x;
    if (i < NX) {
        float v = x[i];
        __half h = __float2half_rn(v);
        g_x16h[i] = h;
        g_x16l[i] = __float2half_rn(v - __half2float(h));
    } else if (i < NX + NW) {
        g_wqkv16[i - NX] = __float2half_rn(wqkv[i - NX]);
    } else if (i < NX + NW + NP) {
        g_wproj16[i - NX - NW] = __float2half_rn(wproj[i - NX - NW]);
    }
}

// ---------------- kernel 0c: edge -> G16 = sigmoid(.)*bias*log2e (fp16) ----------------
__global__ __launch_bounds__(256) void edge_prep_kernel(const float* __restrict__ edge,
                                                        const float* __restrict__ w_ep,
                                                        const float* __restrict__ w_eg,
                                                        const float* __restrict__ b_eg) {
    const int m = blockIdx.x * 256 + threadIdx.x;
    const int n = blockIdx.y, b = blockIdx.z;
    const float* ep = edge + ((size_t)(b * NN + n) * NN + m) * EE;
    float e0 = __ldg(ep), e1 = __ldg(ep + 1), e2 = __ldg(ep + 2),
          e3 = __ldg(ep + 3), e4 = __ldg(ep + 4);
#pragma unroll
    for (int h = 0; h < HH; h++) {
        float biasv = e0 * __ldg(&w_ep[h * EE + 0]);
        biasv = fmaf(e1, __ldg(&w_ep[h * EE + 1]), biasv);
        biasv = fmaf(e2, __ldg(&w_ep[h * EE + 2]), biasv);
        biasv = fmaf(e3, __ldg(&w_ep[h * EE + 3]), biasv);
        biasv = fmaf(e4, __ldg(&w_ep[h * EE + 4]), biasv);
        float gv = fmaf(e0, __ldg(&w_eg[h * EE + 0]), __ldg(&b_eg[h]));
        gv = fmaf(e1, __ldg(&w_eg[h * EE + 1]), gv);
        gv = fmaf(e2, __ldg(&w_eg[h * EE + 2]), gv);
        gv = fmaf(e3, __ldg(&w_eg[h * EE + 3]), gv);
        gv = fmaf(e4, __ldg(&w_eg[h * EE + 4]), gv);
        float gate = __fdividef(1.f, 1.f + __expf(-gv));
        g_G16[((size_t)(b * HH + h) * NN + n) * NN + m] = __float2half(gate * biasv * L2E);
    }
}

// ---------------- mma.sync fp16x2 GEMM: D = (Ah+Al) @ Bh^T, 2 K-passes ----------------
// NC = 16 chunks (seg0: Ah, seg1: Al; B identical both passes). 33% fewer
// mma/ldsm/barriers than bf16x3; per-GEMM rel err ~= fp16 eps ~1e-4.
__global__ __launch_bounds__(256) void mma_gemm_kernel(const float* __restrict__ bias,
                                                       float* __restrict__ outp, int mode) {
    extern __shared__ __align__(128) char sm[];
    const int tid = threadIdx.x;
    const int wid = tid >> 5, lane = tid & 31;
    const int wm = wid >> 1, wn = wid & 1;
    const int mb = blockIdx.y, cb = blockIdx.x;

    const __half* Ah = (mode == 0) ? g_x16h : g_att16h;
    const __half* Al = (mode == 0) ? g_x16l : g_att16l;
    const __half* Bh = (mode == 0) ? g_wqkv16 : g_wproj16;

    const uint32_t sbase = smem_u32(sm);

    int arow[2], axc[2];
#pragma unroll
    for (int mt = 0; mt < 2; mt++) {
        int r = wm * 32 + mt * 16 + (lane & 15);
        arow[mt] = r * 128;
        axc[mt] = r & 7;
    }
    const int akh = lane >> 4;
    int brow[4], bxc[4];
#pragma unroll
    for (int j = 0; j < 4; j++) {
        int r = wn * 64 + j * 16 + ((lane >> 4) << 3) + (lane & 7);
        brow[j] = r * 128;
        bxc[j] = r & 7;
    }
    const int bkh = (lane >> 3) & 1;

    float acc[2][8][4];
#pragma unroll
    for (int mt = 0; mt < 2; mt++)
#pragma unroll
        for (int n8 = 0; n8 < 8; n8++)
#pragma unroll
            for (int q = 0; q < 4; q++) acc[mt][n8][q] = 0.f;

    const int NC = 16;   // 2 segs x 8 k-chunks
    auto load_chunk = [&](int c, int stage) {
        int seg = c >> 3, kc = c & 7;
        const __half* As = seg ? Al : Ah;
        uint32_t st = sbase + stage * 32768;
#pragma unroll
        for (int u8 = 0; u8 < 8; u8++) {
            int u = tid * 8 + u8;
            int isB = u >> 10;
            int uu = u & 1023;
            int r = uu >> 3, ch = uu & 7;
            const __half* src = isB
                ? (Bh + (size_t)(cb * 128 + r) * DD + kc * 64 + ch * 8)
                : (As + (size_t)(mb * 128 + r) * DD + kc * 64 + ch * 8);
            uint32_t sa = st + isB * 16384 + r * 128 + ((ch ^ (r & 7)) << 4);
            cp_async16(sa, src);
        }
        cp_commit();
    };

    load_chunk(0, 0);
    for (int c = 0; c < NC; c++) {
        if (c + 1 < NC) load_chunk(c + 1, (c + 1) & 1);
        if (c + 1 < NC) cp_wait<1>(); else cp_wait<0>();
        __syncthreads();
        uint32_t sA = sbase + (c & 1) * 32768;
        uint32_t sB = sA + 16384;
#pragma unroll
        for (int k16 = 0; k16 < 4; k16++) {
            uint32_t a[2][4];
#pragma unroll
            for (int mt = 0; mt < 2; mt++) {
                uint32_t ad = sA + arow[mt] + (((k16 * 2 + akh) ^ axc[mt]) << 4);
                ldsm4(a[mt][0], a[mt][1], a[mt][2], a[mt][3], ad);
            }
#pragma unroll
            for (int j = 0; j < 4; j++) {
                uint32_t b0, b1, b2, b3;
                uint32_t bd = sB + brow[j] + (((k16 * 2 + bkh) ^ bxc[j]) << 4);
                ldsm4(b0, b1, b2, b3, bd);
                mma16816h(acc[0][2 * j],     a[0][0], a[0][1], a[0][2], a[0][3], b0, b1);
                mma16816h(acc[0][2 * j + 1], a[0][0], a[0][1], a[0][2], a[0][3], b2, b3);
                mma16816h(acc[1][2 * j],     a[1][0], a[1][1], a[1][2], a[1][3], b0, b1);
                mma16816h(acc[1][2 * j + 1], a[1][0], a[1][1], a[1][2], a[1][3], b2, b3);
            }
        }
        __syncthreads();
    }

    const int colw = cb * 128 + wn * 64;
    const int roww = mb * 128 + wm * 32;
#pragma unroll
    for (int mt = 0; mt < 2; mt++) {
#pragma unroll
        for (int n8 = 0; n8 < 8; n8++) {
            int col = colw + n8 * 8 + (lane & 3) * 2;
            int row = roww + mt * 16 + (lane >> 2);
            if (mode == 0) {
                int sect = col >> 9, d = col & 511;
                int h2 = d >> 6, hd = d & 63;
                int b2 = row >> 10, n = row & 1023;
                if (sect < 2) {
                    // Q/K: swizzled fp16 single
                    __half* dst = (sect == 0) ? g_q16 : g_k16;
                    int ch = (hd >> 3) ^ (row & 7);
                    size_t e0 = ((size_t)(b2 * HH + h2) * NN + n) * HDIM + (ch << 3) + (hd & 7);
                    *(uint32_t*)&dst[e0] = pack_h2(acc[mt][n8][0], acc[mt][n8][1]);
                    *(uint32_t*)&dst[e0 + 8 * HDIM] = pack_h2(acc[mt][n8][2], acc[mt][n8][3]);
                } else {
                    size_t base = ((size_t)(b2 * HH + h2) * NN + n) * HDIM + hd;
                    *(float2*)&g_v[base] = make_float2(acc[mt][n8][0], acc[mt][n8][1]);
                    *(float2*)&g_v[base + 8 * HDIM] = make_float2(acc[mt][n8][2], acc[mt][n8][3]);
                }
            } else {
                float b0 = bias[col], b1 = bias[col + 1];
                *(float2*)&outp[(size_t)row * DD + col] =
                    make_float2(acc[mt][n8][0] + b0, acc[mt][n8][1] + b1);
                *(float2*)&outp[(size_t)(row + 8) * DD + col] =
                    make_float2(acc[mt][n8][2] + b0, acc[mt][n8][3] + b1);
            }
        }
    }
}

// ---------------- kernel 1b: V transpose -> pre-swizzled fp16 tiles ----------------
__global__ __launch_bounds__(256) void vprep_kernel() {
    __shared__ float Vf[64][68];
    const int t = blockIdx.x, bh = blockIdx.y;
    const int tid = threadIdx.x;
    const int m0 = t * KT;
    const float* src = g_v + ((size_t)bh * NN + m0) * HDIM;
    for (int u = tid; u < 1024; u += 256) {
        int key = u >> 4, c4 = (u & 15) * 4;
        *(float4*)&Vf[key][c4] = *(const float4*)(src + key * HDIM + c4);
    }
    __syncthreads();
    __half* dh = g_vt16 + (((size_t)bh * NTILES + t) * 64) * 64;
    for (int u = tid; u < 1024; u += 256) {
        int d = u >> 4, k4 = (u & 15) * 4;
        uint32_t h0 = pack_h2(Vf[k4 + 0][d], Vf[k4 + 1][d]);
        uint32_t h1 = pack_h2(Vf[k4 + 2][d], Vf[k4 + 3][d]);
        int chp = (k4 >> 3) ^ (d & 7);
        size_t off = (size_t)d * 64 + (chp << 3) + (k4 & 7);
        *(uint2*)&dh[off] = make_uint2(h0, h1);
    }
}

// ---------------- kernel 2: fp16 tensor-core edge-aware flash attention ----------------
__global__ __launch_bounds__(256, 2) void attn_kernel() {
    extern __shared__ __align__(128) char smraw[];
    const uint32_t sb = smem_u32(smraw);
    const uint32_t uQ = sb;
    int* skm = (int*)(smraw + 49152);

    const int b = blockIdx.z, h = blockIdx.y, qt = blockIdx.x;
    const int bh = b * HH + h;
    const int n0 = qt * QT;
    const int tid = threadIdx.x;
    const int lane = tid & 31;
    const int w = tid >> 5;
    const int wq0 = w * 16;
    const float SCALE = 0.125f * L2E;

    const int anyv = g_any[b];

    const __half* q16 = g_q16 + ((size_t)bh * NN + n0) * HDIM;
    const __half* k16 = g_k16 + (size_t)bh * NN * HDIM;
    const __half* v16 = g_vt16 + (size_t)bh * NN * HDIM;

    auto issue_tile = [&](int t, int st) {
        uint32_t base = sb + 16384 + st * 16384;
        size_t ko = (size_t)t * KT * HDIM;
#pragma unroll
        for (int i = 0; i < 2; i++) {
            int u = tid * 2 + i;
            cp_async16(base + u * 16, k16 + ko + u * 8);
            cp_async16(base + 8192 + u * 16, v16 + ko + u * 8);
        }
        if (tid < 16) cp_async16(smem_u32(skm + st * 64) + tid * 16,
                                 g_mask + b * NN + t * KT + tid * 4);
    };

#pragma unroll
    for (int i = 0; i < 4; i++) {
        int u = tid * 4 + i;
        cp_async16(uQ + u * 16, q16 + u * 8);
    }
    issue_tile(0, 0);
    cp_commit();
    issue_tile(1, 1);
    cp_commit();

    const int r_lo = lane >> 2;
    const int nr0 = n0 + wq0 + r_lo;
    const int nr1 = nr0 + 8;
    const int qv0 = g_mask[b * NN + nr0];
    const int qv1 = g_mask[b * NN + nr1];
    const bool rowv0 = qv0 && anyv;
    const bool rowv1 = qv1 && anyv;

    float accO[8][4];
#pragma unroll
    for (int j = 0; j < 8; j++)
#pragma unroll
        for (int q = 0; q < 4; q++) accO[j][q] = 0.f;
    float mr0 = -1e30f, mr1 = -1e30f, sr0 = 0.f, sr1 = 0.f;

    const __half* Grow0 = g_G16 + ((size_t)bh * NN + nr0) * NN;
    const __half* Grow1 = g_G16 + ((size_t)bh * NN + nr1) * NN;

    for (int t = 0; t < NTILES; t++) {
        cp_wait<1>();
        __syncthreads();
        const int st = t & 1;
        const int m0 = t * KT;
        const uint32_t uK = sb + 16384 + st * 16384;
        const uint32_t uV = uK + 8192;
        const int* skm_st = skm + st * 64;

        float accS[8][4];
#pragma unroll
        for (int j = 0; j < 8; j++)
#pragma unroll
            for (int q = 0; q < 4; q++) accS[j][q] = 0.f;

#pragma unroll
        for (int s = 0; s < 4; s++) {
            int ra = wq0 + (lane & 15);
            int cha = (s * 2 + (lane >> 4)) ^ (ra & 7);
            uint32_t aoff = (uint32_t)(ra * 64 + (cha << 3)) * 2;
            uint32_t ah0, ah1, ah2, ah3;
            ldsm4(ah0, ah1, ah2, ah3, uQ + aoff);
            int rb = ((lane >> 4) << 3) + (lane & 7);
            int khb = s * 2 + ((lane >> 3) & 1);
#pragma unroll
            for (int g = 0; g < 4; g++) {
                int rn = g * 16 + rb;
                uint32_t boff = (uint32_t)(rn * 64 + ((khb ^ (rn & 7)) << 3)) * 2;
                uint32_t bh0, bh1, bh2, bh3;
                ldsm4(bh0, bh1, bh2, bh3, uK + boff);
                mma16816h(accS[2 * g],     ah0, ah1, ah2, ah3, bh0, bh1);
                mma16816h(accS[2 * g + 1], ah0, ah1, ah2, ah3, bh2, bh3);
            }
        }

#pragma unroll
        for (int j = 0; j < 8; j++) {
            int colL = j * 8 + (lane & 3) * 2;
            int cg = m0 + colL;
            int kv0 = skm_st[colL], kv1 = skm_st[colL + 1];
            float2 gv0 = __half22float2(__ldg((const __half2*)(Grow0 + cg)));
            float2 gv1 = __half22float2(__ldg((const __half2*)(Grow1 + cg)));
            float s00 = fmaf(accS[j][0], SCALE, gv0.x);
            float s01 = fmaf(accS[j][1], SCALE, gv0.y);
            float s10 = fmaf(accS[j][2], SCALE, gv1.x);
            float s11 = fmaf(accS[j][3], SCALE, gv1.y);
            accS[j][0] = rowv0 ? (kv0 ? s00 : -1e30f) : 0.0f;
            accS[j][1] = rowv0 ? (kv1 ? s01 : -1e30f) : 0.0f;
            accS[j][2] = rowv1 ? (kv0 ? s10 : -1e30f) : 0.0f;
            accS[j][3] = rowv1 ? (kv1 ? s11 : -1e30f) : 0.0f;
        }

        float mx0 = -1e30f, mx1 = -1e30f;
#pragma unroll
        for (int j = 0; j < 8; j++) {
            mx0 = fmaxf(mx0, fmaxf(accS[j][0], accS[j][1]));
            mx1 = fmaxf(mx1, fmaxf(accS[j][2], accS[j][3]));
        }
        mx0 = fmaxf(mx0, __shfl_xor_sync(0xffffffffu, mx0, 1));
        mx0 = fmaxf(mx0, __shfl_xor_sync(0xffffffffu, mx0, 2));
        mx1 = fmaxf(mx1, __shfl_xor_sync(0xffffffffu, mx1, 1));
        mx1 = fmaxf(mx1, __shfl_xor_sync(0xffffffffu, mx1, 2));
        float mn0 = fmaxf(mr0, mx0), mn1 = fmaxf(mr1, mx1);
        float al0 = fexp2(mr0 - mn0), al1 = fexp2(mr1 - mn1);
        mr0 = mn0; mr1 = mn1;
        float ls0 = 0.f, ls1 = 0.f;
#pragma unroll
        for (int j = 0; j < 8; j++) {
            accS[j][0] = fexp2(accS[j][0] - mn0);
            accS[j][1] = fexp2(accS[j][1] - mn0);
            accS[j][2] = fexp2(accS[j][2] - mn1);
            accS[j][3] = fexp2(accS[j][3] - mn1);
            ls0 += accS[j][0] + accS[j][1];
            ls1 += accS[j][2] + accS[j][3];
        }
        ls0 += __shfl_xor_sync(0xffffffffu, ls0, 1);
        ls0 += __shfl_xor_sync(0xffffffffu, ls0, 2);
        ls1 += __shfl_xor_sync(0xffffffffu, ls1, 1);
        ls1 += __shfl_xor_sync(0xffffffffu, ls1, 2);
        sr0 = fmaf(sr0, al0, ls0);
        sr1 = fmaf(sr1, al1, ls1);
#pragma unroll
        for (int j = 0; j < 8; j++) {
            accO[j][0] *= al0; accO[j][1] *= al0;
            accO[j][2] *= al1; accO[j][3] *= al1;
        }

#pragma unroll
        for (int tt = 0; tt < 4; tt++) {
            uint32_t ah0 = pack_h2(accS[2 * tt][0],     accS[2 * tt][1]);
            uint32_t ah1 = pack_h2(accS[2 * tt][2],     accS[2 * tt][3]);
            uint32_t ah2 = pack_h2(accS[2 * tt + 1][0], accS[2 * tt + 1][1]);
            uint32_t ah3 = pack_h2(accS[2 * tt + 1][2], accS[2 * tt + 1][3]);
            int rb = ((lane >> 4) << 3) + (lane & 7);
            int khb = tt * 2 + ((lane >> 3) & 1);
#pragma unroll
            for (int g = 0; g < 4; g++) {
                int rn = g * 16 + rb;
                uint32_t boff = (uint32_t)(rn * 64 + ((khb ^ (rn & 7)) << 3)) * 2;
                uint32_t bh0, bh1, bh2, bh3;
                ldsm4(bh0, bh1, bh2, bh3, uV + boff);
                mma16816h(accO[2 * g],     ah0, ah1, ah2, ah3, bh0, bh1);
                mma16816h(accO[2 * g + 1], ah0, ah1, ah2, ah3, bh2, bh3);
            }
        }

        __syncthreads();
        if (t + 2 < NTILES) issue_tile(t + 2, st);
        cp_commit();
    }

    // ---- final: normalize + emit fp16 hi/lo for proj GEMM ----
    float inv0 = __fdividef(1.f, sr0), inv1 = __fdividef(1.f, sr1);
#pragma unroll
    for (int j = 0; j < 8; j++) {
        int d0 = j * 8 + (lane & 3) * 2;
        size_t b0i = (size_t)(b * NN + nr0) * DD + h * HDIM + d0;
        size_t b1i = (size_t)(b * NN + nr1) * DD + h * HDIM + d0;
        uint32_t hi, lo;
        pack_hilo16(accO[j][0] * inv0, accO[j][1] * inv0, hi, lo);
        *(uint32_t*)&g_att16h[b0i] = hi;
        *(uint32_t*)&g_att16l[b0i] = lo;
        pack_hilo16(accO[j][2] * inv1, accO[j][3] * inv1, hi, lo);
        *(uint32_t*)&g_att16h[b1i] = hi;
        *(uint32_t*)&g_att16l[b1i] = lo;
    }
}

// ---------------- launch ----------------
extern "C" void kernel_launch(void* const* d_in, const int* in_sizes, int n_in,
                              void* d_out, int out_size) {
    const float* x      = (const float*)d_in[0];
    const float* edge   = (const float*)d_in[1];
    const void*  mask   = d_in[2];
    const float* w_qkv  = (const float*)d_in[3];
    const float* w_ep   = (const float*)d_in[4];
    const float* w_eg   = (const float*)d_in[5];
    const float* b_eg   = (const float*)d_in[6];
    const float* w_proj = (const float*)d_in[7];
    const float* b_proj = (const float*)d_in[8];
    float* out = (float*)d_out;

    static bool attr_done = false;
    if (!attr_done) {
        cudaFuncSetAttribute(mma_gemm_kernel, cudaFuncAttributeMaxDynamicSharedMemorySize, 65536);
        cudaFuncSetAttribute(attn_kernel, cudaFuncAttributeMaxDynamicSharedMemorySize, 49664);
        attr_done = true;
    }

    mask_prep_kernel<<<1, 1024>>>((const unsigned*)mask);

    cvt_all_kernel<<<(NX + NW + NP + 255) / 256, 256>>>(x, w_qkv, w_proj);

    dim3 ge(NN / 256, NN, BB);
    edge_prep_kernel<<<ge, 256>>>(edge, w_ep, w_eg, b_eg);

    dim3 g1(12, 32);
    mma_gemm_kernel<<<g1, 256, 65536>>>(nullptr, nullptr, 0);

    dim3 gv(NTILES, BB * HH);
    vprep_kernel<<<gv, 256>>>();

    dim3 ga(NN / QT, HH, BB);
    attn_kernel<<<ga, 256, 49664>>>();

    dim3 g2(4, 32);
    mma_gemm_kernel<<<g2, 256, 65536>>>(b_proj, out, 1);
}